// round 7
// baseline (speedup 1.0000x reference)
#include <cuda_runtime.h>
#include <cstdint>

#define BB 128
#define SS 512
#define EE 512
#define HH 1024
#define TOK (BB*SS)
#define NCTA 128

// Scratch (allocation-free rule: __device__ globals)
__device__ float g_pre[(size_t)TOK * HH];        // [s*B + b][h], fp32
__device__ float g_h[BB * HH];                   // final hidden state (written at t=511)
__device__ unsigned g_ha[2][4][8][2][4096];      // [buf][mgroup][chunk][hi/lo][frag words]
__device__ unsigned g_arrive[NCTA];              // per-CTA monotonic barrier flags

__device__ __forceinline__ unsigned f2tf(float f){
  unsigned u; asm("cvt.rna.tf32.f32 %0, %1;" : "=r"(u) : "f"(f)); return u;
}

__device__ __forceinline__ void mma8(float c[4], unsigned a0,unsigned a1,unsigned a2,unsigned a3,
                                     unsigned b0,unsigned b1){
  asm volatile("mma.sync.aligned.m16n8k8.row.col.f32.tf32.tf32.f32 "
    "{%0,%1,%2,%3}, {%4,%5,%6,%7}, {%8,%9}, {%0,%1,%2,%3};"
    : "+f"(c[0]),"+f"(c[1]),"+f"(c[2]),"+f"(c[3])
    : "r"(a0),"r"(a1),"r"(a2),"r"(a3),"r"(b0),"r"(b1));
}

__global__ void k_init(){
  int i = blockIdx.x*blockDim.x + threadIdx.x;
  // zero packed-A buffer 0 (read at t=0; h0 = 0)
  if (i < 4*8*2*4096) ((unsigned*)g_ha)[i] = 0u;
  if (i < NCTA) g_arrive[i] = 0u;
}

// pre[s*B+b][h] = dot(emb[x[b][s]], W[h]) + Wb[h]   (M=65536, N=1024, K=512)
__global__ __launch_bounds__(256) void k_pre(const int* __restrict__ x, const float* __restrict__ emb,
                                             const float* __restrict__ Ww, const float* __restrict__ Wb){
  __shared__ unsigned As[64][33];
  __shared__ unsigned Bsm[64][33];
  __shared__ const float* rowp[64];
  const int tid = threadIdx.x;
  const int m0 = blockIdx.y*64, n0 = blockIdx.x*64;
  if (tid < 64){
    int tok = m0 + tid;
    int b = tok & (BB-1), s = tok >> 7;
    rowp[tid] = emb + (size_t)x[b*SS + s]*EE;
  }
  __syncthreads();
  const int lane = tid & 31, wid = tid >> 5;
  const int wm = wid >> 1, wn = wid & 1;
  const int gr = lane >> 2, gq = lane & 3;
  float acc[4][4];
  #pragma unroll
  for (int i=0;i<4;i++){ acc[i][0]=0.f; acc[i][1]=0.f; acc[i][2]=0.f; acc[i][3]=0.f; }

  for (int kt = 0; kt < EE/32; ++kt){
    const int k0 = kt*32;
    #pragma unroll
    for (int it=0; it<2; ++it){
      int id = tid + it*256;
      int r = id >> 3, c4 = (id & 7)*4;
      float4 v = *(const float4*)(rowp[r] + k0 + c4);
      As[r][c4+0]=f2tf(v.x); As[r][c4+1]=f2tf(v.y); As[r][c4+2]=f2tf(v.z); As[r][c4+3]=f2tf(v.w);
      float4 w = *(const float4*)(Ww + (size_t)(n0+r)*EE + k0 + c4);
      Bsm[r][c4+0]=f2tf(w.x); Bsm[r][c4+1]=f2tf(w.y); Bsm[r][c4+2]=f2tf(w.z); Bsm[r][c4+3]=f2tf(w.w);
    }
    __syncthreads();
    #pragma unroll
    for (int kk=0; kk<4; ++kk){
      unsigned a0 = As[wm*16+gr  ][kk*8+gq];
      unsigned a1 = As[wm*16+gr+8][kk*8+gq];
      unsigned a2 = As[wm*16+gr  ][kk*8+gq+4];
      unsigned a3 = As[wm*16+gr+8][kk*8+gq+4];
      #pragma unroll
      for (int nf=0; nf<4; ++nf){
        int nr = wn*32 + nf*8 + gr;
        mma8(acc[nf], a0,a1,a2,a3, Bsm[nr][kk*8+gq], Bsm[nr][kk*8+gq+4]);
      }
    }
    __syncthreads();
  }
  #pragma unroll
  for (int nf=0; nf<4; ++nf){
    int nc = n0 + wn*32 + nf*8 + 2*gq;
    int mr = m0 + wm*16 + gr;
    float wb0 = Wb[nc], wb1 = Wb[nc+1];
    g_pre[(size_t)mr*HH + nc]        = acc[nf][0] + wb0;
    g_pre[(size_t)mr*HH + nc + 1]    = acc[nf][1] + wb1;
    g_pre[(size_t)(mr+8)*HH + nc]    = acc[nf][2] + wb0;
    g_pre[(size_t)(mr+8)*HH + nc+1]  = acc[nf][3] + wb1;
  }
}

// ---------------- persistent recurrence kernel ----------------
// 128 CTAs = 4 (M, 32 rows) x 32 (N, 32 cols), 1/SM, 256 threads, 8 warps.
// A (h) is pre-split hi/lo tf32 in MMA fragment layout, packed by the PRODUCER
// of the previous step into g_ha (ping-pong). Hot loop: LDS.128 x2 + LDS.64 + 2 HMMA.
// SMEM words: Bp [0,32768) packed U; Apack [32768, 32768+2*8192) double-buffered.
#define SM_BP    0
#define SM_AP    32768
#define SMEM_WORDS (32768 + 2*8192)

__device__ __forceinline__ void cpa16(unsigned* dst_sm, const unsigned* src){
  uint32_t sa = (uint32_t)__cvta_generic_to_shared(dst_sm);
  asm volatile("cp.async.cg.shared.global [%0], [%1], 16;" :: "r"(sa), "l"(src));
}

__global__ __launch_bounds__(256, 1) void k_scan(const float* __restrict__ U, const float* __restrict__ Ub){
  extern __shared__ unsigned smw[];
  const int tid = threadIdx.x, lane = tid & 31, wid = tid >> 5;
  const int gr = lane >> 2, gq = lane & 3;
  const int wm = wid & 1, wn = wid >> 1;        // 2 m-halves x 4 n-blocks, warp tile 16x8
  const int bx = blockIdx.x, by = blockIdx.y;
  const int m0 = by*32, n0 = bx*32;
  const int cta = by*32 + bx;

  // ---- pack U slice (rows n0..n0+31 of U, full K) into tf32 B-fragments ----
  for (int e = tid; e < 32*HH; e += 256){
    int n = e >> 10, k = e & (HH-1);
    float v = U[(size_t)(n0+n)*HH + k];
    int g = k >> 3, kk = k & 7;
    int w = ((g*4 + (n>>3))*32 + (n&7)*4 + (kk&3))*2 + (kk>>2);
    smw[SM_BP + w] = f2tf(v);
  }
  const int nc = n0 + wn*8 + 2*gq;
  const int mr = m0 + wm*16 + gr;
  const float ub0 = Ub[nc], ub1 = Ub[nc+1];
  // packed-write constants (this thread produces h[mr][nc], h[mr+8][nc], h[mr][nc+1], h[mr+8][nc+1])
  const int wchunk = nc >> 7;                   // destination chunk of column nc
  const int kin = nc & 127;
  const int wkb = kin >> 3;
  const int kk0 = kin & 7;                      // = 2*gq mod 8
  const int khalf = kk0 >> 2;
  const int slot = (wkb*2 + wm)*32 + gr*4 + (kk0 & 3);
  __syncthreads();

  for (int t = 0; t < SS; ++t){
    const unsigned (*ha_r)[2][4096] = g_ha[t & 1][by];          // [chunk][hi/lo][4096]
    unsigned (*ha_w)[2][4096] = g_ha[(t & 1) ^ 1][by? 0:0];     // placeholder; real below
    const float* __restrict__ pre = g_pre + (size_t)t*BB*HH;

    const float pv0 = pre[(size_t)mr*HH + nc];
    const float pv1 = pre[(size_t)mr*HH + nc + 1];
    const float pv2 = pre[(size_t)(mr+8)*HH + nc];
    const float pv3 = pre[(size_t)(mr+8)*HH + nc + 1];
    float accH[4] = {0.f,0.f,0.f,0.f};
    float accL[4] = {0.f,0.f,0.f,0.f};

    // prefetch chunk 0 packed fragments (hi+lo = 8192 words = 32KB)
    {
      const unsigned* src = &ha_r[0][0][0];
      #pragma unroll
      for (int i=0;i<8;++i){ int idx = (tid + i*256)*4; cpa16(smw + SM_AP + idx, src + idx); }
      asm volatile("cp.async.commit_group;");
    }

    #pragma unroll 1
    for (int c = 0; c < 8; ++c){
      if (c < 7){
        const unsigned* src = &ha_r[c+1][0][0];
        unsigned* dst = smw + SM_AP + ((c+1)&1)*8192;
        #pragma unroll
        for (int i=0;i<8;++i){ int idx = (tid + i*256)*4; cpa16(dst + idx, src + idx); }
        asm volatile("cp.async.commit_group;");
        asm volatile("cp.async.wait_group 1;" ::: "memory");
      } else {
        asm volatile("cp.async.wait_group 0;" ::: "memory");
      }
      __syncthreads();   // Apack[c&1] ready

      const unsigned* ap = smw + SM_AP + (c&1)*8192;
      const unsigned* bp = smw + SM_BP + c*4096 + (wn*32 + lane)*2;
      #pragma unroll
      for (int kb = 0; kb < 16; ++kb){
        unsigned off = (unsigned)((kb*2 + wm)*32 + lane)*4;
        uint4 ah = *(const uint4*)(ap + off);
        uint4 al = *(const uint4*)(ap + 4096 + off);
        uint2 bb = *(const uint2*)(bp + kb*256);
        mma8(accH, ah.x,ah.y,ah.z,ah.w, bb.x, bb.y);
        mma8(accL, al.x,al.y,al.z,al.w, bb.x, bb.y);
      }
      __syncthreads();   // all warps done with Apack[c&1] before refill
    }

    // epilogue: h = tanh(acc + pre + Ub); emit hi/lo fragments for next step
    float o00 = tanhf(accH[0] + accL[0] + pv0 + ub0);   // (mr,   nc)
    float o01 = tanhf(accH[1] + accL[1] + pv1 + ub1);   // (mr,   nc+1)
    float o10 = tanhf(accH[2] + accL[2] + pv2 + ub0);   // (mr+8, nc)
    float o11 = tanhf(accH[3] + accL[3] + pv3 + ub1);   // (mr+8, nc+1)

    if (t < SS-1){
      unsigned* hi = &g_ha[(t & 1) ^ 1][by][wchunk][0][0];
      unsigned* lo = &g_ha[(t & 1) ^ 1][by][wchunk][1][0];
      unsigned h00=f2tf(o00), h10=f2tf(o10), h01=f2tf(o01), h11=f2tf(o11);
      unsigned l00=f2tf(o00-__uint_as_float(h00));
      unsigned l10=f2tf(o10-__uint_as_float(h10));
      unsigned l01=f2tf(o01-__uint_as_float(h01));
      unsigned l11=f2tf(o11-__uint_as_float(h11));
      // word layout: slot*4 + (h' + 2*khalf); (v(m,k), v(m+8,k)) are adjacent words
      *(uint2*)(hi + slot*4     + 2*khalf) = make_uint2(h00, h10);
      *(uint2*)(hi + (slot+1)*4 + 2*khalf) = make_uint2(h01, h11);
      *(uint2*)(lo + slot*4     + 2*khalf) = make_uint2(l00, l10);
      *(uint2*)(lo + (slot+1)*4 + 2*khalf) = make_uint2(l01, l11);
    } else {
      g_h[(size_t)mr*HH + nc]       = o00;
      g_h[(size_t)mr*HH + nc + 1]   = o01;
      g_h[(size_t)(mr+8)*HH + nc]   = o10;
      g_h[(size_t)(mr+8)*HH + nc+1] = o11;
    }

    // distributed flag barrier across 128 CTAs (monotonic, no atomics)
    if (t < SS-1){
      __threadfence();
      __syncthreads();
      if (tid == 0) *((volatile unsigned*)&g_arrive[cta]) = (unsigned)(t+1);
      if (tid < NCTA){
        volatile unsigned* f = &g_arrive[tid];
        while (*f <= (unsigned)t) { }
      }
      __syncthreads();
      __threadfence();
    }
    (void)ha_w;
  }
}

__global__ void k_final(const float* __restrict__ Vw, const float* __restrict__ Vb, float* __restrict__ out){
  int b = blockIdx.x;
  const float* h = g_h + (size_t)b*HH;
  float s = 0.f;
  for (int k = threadIdx.x; k < HH; k += 128) s += h[k]*Vw[k];
  #pragma unroll
  for (int o=16;o;o>>=1) s += __shfl_down_sync(0xffffffffu, s, o);
  __shared__ float red[4];
  if ((threadIdx.x & 31) == 0) red[threadIdx.x>>5] = s;
  __syncthreads();
  if (threadIdx.x == 0){
    float tot = red[0]+red[1]+red[2]+red[3] + Vb[0];
    out[b] = 1.f/(1.f + expf(-tot));
  }
}

extern "C" void kernel_launch(void* const* d_in, const int* in_sizes, int n_in,
                              void* d_out, int out_size){
  (void)in_sizes; (void)n_in; (void)out_size;
  const int*   x   = (const int*)d_in[0];
  const float* emb = (const float*)d_in[1];
  const float* Ww  = (const float*)d_in[2];
  const float* Wb  = (const float*)d_in[3];
  const float* Uw  = (const float*)d_in[4];
  const float* Ubv = (const float*)d_in[5];
  const float* Vw  = (const float*)d_in[6];
  const float* Vb  = (const float*)d_in[7];
  float* out = (float*)d_out;

  static bool attr_done = false;
  if (!attr_done){
    cudaFuncSetAttribute(k_scan, cudaFuncAttributeMaxDynamicSharedMemorySize, SMEM_WORDS*4);
    attr_done = true;
  }

  k_init<<<1024, 256>>>();
  k_pre<<<dim3(HH/64, TOK/64), 256>>>(x, emb, Ww, Wb);
  k_scan<<<dim3(32, 4), 256, SMEM_WORDS*4>>>(Uw, Ubv);
  k_final<<<BB, 128>>>(Vw, Vb, out);
}

// round 8
// speedup vs baseline: 1.1099x; 1.1099x over previous
#include <cuda_runtime.h>
#include <cstdint>

#define BB 128
#define SS 512
#define EE 512
#define HH 1024
#define TOK (BB*SS)
#define NCTA 128

// Scratch (allocation-free rule: __device__ globals)
__device__ float g_pre[(size_t)TOK * HH];        // [s*B + b][h], fp32
__device__ float g_h[BB * HH];                   // final hidden state (written at t=511)
__device__ unsigned g_ha[2][4][8][2][4096];      // [buf][mgroup][chunk][hi/lo][frag words]
__device__ unsigned g_arrive[NCTA];              // per-CTA monotonic barrier flags

__device__ __forceinline__ unsigned f2tf(float f){
  unsigned u; asm("cvt.rna.tf32.f32 %0, %1;" : "=r"(u) : "f"(f)); return u;
}

__device__ __forceinline__ void mma8(float c[4], unsigned a0,unsigned a1,unsigned a2,unsigned a3,
                                     unsigned b0,unsigned b1){
  asm volatile("mma.sync.aligned.m16n8k8.row.col.f32.tf32.tf32.f32 "
    "{%0,%1,%2,%3}, {%4,%5,%6,%7}, {%8,%9}, {%0,%1,%2,%3};"
    : "+f"(c[0]),"+f"(c[1]),"+f"(c[2]),"+f"(c[3])
    : "r"(a0),"r"(a1),"r"(a2),"r"(a3),"r"(b0),"r"(b1));
}

__global__ void k_init(){
  int i = blockIdx.x*blockDim.x + threadIdx.x;
  // zero packed-A buffer 0 (read at t=0; h0 = 0)
  if (i < 4*8*2*4096) ((unsigned*)g_ha)[i] = 0u;
  if (i < NCTA) g_arrive[i] = 0u;
}

// pre[s*B+b][h] = dot(emb[x[b][s]], W[h]) + Wb[h]   (M=65536, N=1024, K=512)
__global__ __launch_bounds__(256) void k_pre(const int* __restrict__ x, const float* __restrict__ emb,
                                             const float* __restrict__ Ww, const float* __restrict__ Wb){
  __shared__ unsigned As[64][33];
  __shared__ unsigned Bsm[64][33];
  __shared__ const float* rowp[64];
  const int tid = threadIdx.x;
  const int m0 = blockIdx.y*64, n0 = blockIdx.x*64;
  if (tid < 64){
    int tok = m0 + tid;
    int b = tok & (BB-1), s = tok >> 7;
    rowp[tid] = emb + (size_t)x[b*SS + s]*EE;
  }
  __syncthreads();
  const int lane = tid & 31, wid = tid >> 5;
  const int wm = wid >> 1, wn = wid & 1;
  const int gr = lane >> 2, gq = lane & 3;
  float acc[4][4];
  #pragma unroll
  for (int i=0;i<4;i++){ acc[i][0]=0.f; acc[i][1]=0.f; acc[i][2]=0.f; acc[i][3]=0.f; }

  for (int kt = 0; kt < EE/32; ++kt){
    const int k0 = kt*32;
    #pragma unroll
    for (int it=0; it<2; ++it){
      int id = tid + it*256;
      int r = id >> 3, c4 = (id & 7)*4;
      float4 v = *(const float4*)(rowp[r] + k0 + c4);
      As[r][c4+0]=f2tf(v.x); As[r][c4+1]=f2tf(v.y); As[r][c4+2]=f2tf(v.z); As[r][c4+3]=f2tf(v.w);
      float4 w = *(const float4*)(Ww + (size_t)(n0+r)*EE + k0 + c4);
      Bsm[r][c4+0]=f2tf(w.x); Bsm[r][c4+1]=f2tf(w.y); Bsm[r][c4+2]=f2tf(w.z); Bsm[r][c4+3]=f2tf(w.w);
    }
    __syncthreads();
    #pragma unroll
    for (int kk=0; kk<4; ++kk){
      unsigned a0 = As[wm*16+gr  ][kk*8+gq];
      unsigned a1 = As[wm*16+gr+8][kk*8+gq];
      unsigned a2 = As[wm*16+gr  ][kk*8+gq+4];
      unsigned a3 = As[wm*16+gr+8][kk*8+gq+4];
      #pragma unroll
      for (int nf=0; nf<4; ++nf){
        int nr = wn*32 + nf*8 + gr;
        mma8(acc[nf], a0,a1,a2,a3, Bsm[nr][kk*8+gq], Bsm[nr][kk*8+gq+4]);
      }
    }
    __syncthreads();
  }
  #pragma unroll
  for (int nf=0; nf<4; ++nf){
    int nc = n0 + wn*32 + nf*8 + 2*gq;
    int mr = m0 + wm*16 + gr;
    float wb0 = Wb[nc], wb1 = Wb[nc+1];
    g_pre[(size_t)mr*HH + nc]        = acc[nf][0] + wb0;
    g_pre[(size_t)mr*HH + nc + 1]    = acc[nf][1] + wb1;
    g_pre[(size_t)(mr+8)*HH + nc]    = acc[nf][2] + wb0;
    g_pre[(size_t)(mr+8)*HH + nc+1]  = acc[nf][3] + wb1;
  }
}

// ---------------- persistent recurrence kernel ----------------
// 128 CTAs = 4 (M, 32 rows) x 32 (N, 32 cols), 1/SM, 256 threads, 8 warps.
// Warps: wm = wid&1 (m-half), wks = wid>>1 (k-quarter of each 128-k chunk).
// Warp tile m16 x n32 x k32: A fragments read ONCE, B twice -> 64KB SMEM/chunk.
// A (h) pre-split hi/lo tf32 packed by producer into g_ha (R7-proven layout).
// SMEM words: Bp [0,32768) packed U; Apack [32768, 32768+2*8192) double-buffered;
// epilogue k-reduction reuses Apack area.
#define SM_BP    0
#define SM_AP    32768
#define SMEM_WORDS (32768 + 2*8192)

__device__ __forceinline__ void cpa16(unsigned* dst_sm, const unsigned* src){
  uint32_t sa = (uint32_t)__cvta_generic_to_shared(dst_sm);
  asm volatile("cp.async.cg.shared.global [%0], [%1], 16;" :: "r"(sa), "l"(src));
}

__global__ __launch_bounds__(256, 1) void k_scan(const float* __restrict__ U, const float* __restrict__ Ub){
  extern __shared__ unsigned smw[];
  const int tid = threadIdx.x, lane = tid & 31, wid = tid >> 5;
  const int gr = lane >> 2, gq = lane & 3;
  const int wm = wid & 1, wks = wid >> 1;       // 2 m-halves x 4 k-quarters
  const int bx = blockIdx.x, by = blockIdx.y;
  const int m0 = by*32, n0 = bx*32;
  const int cta = by*32 + bx;

  // ---- pack U slice (rows n0..n0+31 of U, full K) into tf32 B-fragments ----
  // (n,k) -> word ((g*4 + (n>>3))*32 + (n&7)*4 + (kk&3))*2 + (kk>>2); g=k>>3, kk=k&7
  for (int e = tid; e < 32*HH; e += 256){
    int n = e >> 10, k = e & (HH-1);
    float v = U[(size_t)(n0+n)*HH + k];
    int g = k >> 3, kk = k & 7;
    int w = ((g*4 + (n>>3))*32 + (n&7)*4 + (kk&3))*2 + (kk>>2);
    smw[SM_BP + w] = f2tf(v);
  }
  // this warp's epilogue n-fragment: nf = wks
  const int nc = n0 + wks*8 + 2*gq;
  const int mr = m0 + wm*16 + gr;
  const float ub0 = Ub[nc], ub1 = Ub[nc+1];
  // packed-write constants (R7-proven mapping) for values (mr,nc),(mr,nc+1),(mr+8,nc),(mr+8,nc+1)
  const int wchunk = nc >> 7;
  const int kin = nc & 127;
  const int wkb = kin >> 3;
  const int kk0 = kin & 7;
  const int khalf = kk0 >> 2;
  const int slot = (wkb*2 + wm)*32 + gr*4 + (kk0 & 3);
  __syncthreads();

  for (int t = 0; t < SS; ++t){
    const unsigned (*ha_r)[2][4096] = g_ha[t & 1][by];   // [chunk][hi/lo][4096]
    const float* __restrict__ pre = g_pre + (size_t)t*BB*HH;

    // prefetch chunk 0 packed fragments (hi+lo = 8192 words = 32KB)
    {
      const unsigned* src = &ha_r[0][0][0];
      #pragma unroll
      for (int i=0;i<8;++i){ int idx = (tid + i*256)*4; cpa16(smw + SM_AP + idx, src + idx); }
      asm volatile("cp.async.commit_group;");
    }

    const float pv0 = pre[(size_t)mr*HH + nc];
    const float pv1 = pre[(size_t)mr*HH + nc + 1];
    const float pv2 = pre[(size_t)(mr+8)*HH + nc];
    const float pv3 = pre[(size_t)(mr+8)*HH + nc + 1];

    float accH[4][4], accL[4][4];
    #pragma unroll
    for (int i=0;i<4;++i){
      accH[i][0]=0.f;accH[i][1]=0.f;accH[i][2]=0.f;accH[i][3]=0.f;
      accL[i][0]=0.f;accL[i][1]=0.f;accL[i][2]=0.f;accL[i][3]=0.f;
    }

    #pragma unroll 1
    for (int c = 0; c < 8; ++c){
      if (c < 7){
        const unsigned* src = &ha_r[c+1][0][0];
        unsigned* dst = smw + SM_AP + ((c+1)&1)*8192;
        #pragma unroll
        for (int i=0;i<8;++i){ int idx = (tid + i*256)*4; cpa16(dst + idx, src + idx); }
        asm volatile("cp.async.commit_group;");
        asm volatile("cp.async.wait_group 1;" ::: "memory");
      } else {
        asm volatile("cp.async.wait_group 0;" ::: "memory");
      }
      __syncthreads();   // Apack[c&1] ready

      const unsigned* ap = smw + SM_AP + (c&1)*8192;
      #pragma unroll
      for (int kl = 0; kl < 4; ++kl){
        const int kb = wks*4 + kl;                 // k8-group within chunk (0..15)
        unsigned off = (unsigned)((kb*2 + wm)*32 + lane)*4;
        uint4 ah = *(const uint4*)(ap + off);
        uint4 al = *(const uint4*)(ap + 4096 + off);
        const unsigned* bp = smw + SM_BP + ((c*16 + kb)*4*32 + lane)*2;
        #pragma unroll
        for (int nf = 0; nf < 4; ++nf){
          uint2 bb = *(const uint2*)(bp + nf*64);
          mma8(accH[nf], ah.x,ah.y,ah.z,ah.w, bb.x, bb.y);
          mma8(accL[nf], al.x,al.y,al.z,al.w, bb.x, bb.y);
        }
      }
      __syncthreads();   // all warps done with Apack[c&1] before refill
    }

    // ---- k-split reduction via SMEM (Apack area free now) ----
    float* red = (float*)(smw + SM_AP);
    // each warp writes its 16 partial sums (hi+lo combined): [wid][lane][nf][4]
    #pragma unroll
    for (int nf = 0; nf < 4; ++nf){
      float4 v;
      v.x = accH[nf][0] + accL[nf][0];
      v.y = accH[nf][1] + accL[nf][1];
      v.z = accH[nf][2] + accL[nf][2];
      v.w = accH[nf][3] + accL[nf][3];
      *(float4*)(red + ((wid*32 + lane)*4 + nf)*4) = v;
    }
    __syncthreads();
    // warp (wm, wks) reduces nf = wks over the 4 k-quarters
    float s0, s1, s2, s3;
    {
      float4 a0 = *(const float4*)(red + (((0*2+wm)*32 + lane)*4 + wks)*4);
      float4 a1 = *(const float4*)(red + (((1*2+wm)*32 + lane)*4 + wks)*4);
      float4 a2 = *(const float4*)(red + (((2*2+wm)*32 + lane)*4 + wks)*4);
      float4 a3 = *(const float4*)(red + (((3*2+wm)*32 + lane)*4 + wks)*4);
      s0 = (a0.x + a1.x) + (a2.x + a3.x);
      s1 = (a0.y + a1.y) + (a2.y + a3.y);
      s2 = (a0.z + a1.z) + (a2.z + a3.z);
      s3 = (a0.w + a1.w) + (a2.w + a3.w);
    }
    __syncthreads();   // done reading red before next step reuses Apack

    // epilogue: h = tanh(sum + pre + Ub); emit hi/lo fragments for next step
    float o00 = tanhf(s0 + pv0 + ub0);   // (mr,   nc)
    float o01 = tanhf(s1 + pv1 + ub1);   // (mr,   nc+1)
    float o10 = tanhf(s2 + pv2 + ub0);   // (mr+8, nc)
    float o11 = tanhf(s3 + pv3 + ub1);   // (mr+8, nc+1)

    if (t < SS-1){
      unsigned* hi = &g_ha[(t & 1) ^ 1][by][wchunk][0][0];
      unsigned* lo = &g_ha[(t & 1) ^ 1][by][wchunk][1][0];
      unsigned h00=f2tf(o00), h10=f2tf(o10), h01=f2tf(o01), h11=f2tf(o11);
      unsigned l00=f2tf(o00-__uint_as_float(h00));
      unsigned l10=f2tf(o10-__uint_as_float(h10));
      unsigned l01=f2tf(o01-__uint_as_float(h01));
      unsigned l11=f2tf(o11-__uint_as_float(h11));
      *(uint2*)(hi + slot*4     + 2*khalf) = make_uint2(h00, h10);
      *(uint2*)(hi + (slot+1)*4 + 2*khalf) = make_uint2(h01, h11);
      *(uint2*)(lo + slot*4     + 2*khalf) = make_uint2(l00, l10);
      *(uint2*)(lo + (slot+1)*4 + 2*khalf) = make_uint2(l01, l11);
    } else {
      g_h[(size_t)mr*HH + nc]       = o00;
      g_h[(size_t)mr*HH + nc + 1]   = o01;
      g_h[(size_t)(mr+8)*HH + nc]   = o10;
      g_h[(size_t)(mr+8)*HH + nc+1] = o11;
    }

    // distributed flag barrier across 128 CTAs (monotonic, no atomics)
    if (t < SS-1){
      __threadfence();
      __syncthreads();
      if (tid == 0) *((volatile unsigned*)&g_arrive[cta]) = (unsigned)(t+1);
      if (tid < NCTA){
        volatile unsigned* f = &g_arrive[tid];
        while (*f <= (unsigned)t) { }
      }
      __syncthreads();
      __threadfence();
    }
  }
}

__global__ void k_final(const float* __restrict__ Vw, const float* __restrict__ Vb, float* __restrict__ out){
  int b = blockIdx.x;
  const float* h = g_h + (size_t)b*HH;
  float s = 0.f;
  for (int k = threadIdx.x; k < HH; k += 128) s += h[k]*Vw[k];
  #pragma unroll
  for (int o=16;o;o>>=1) s += __shfl_down_sync(0xffffffffu, s, o);
  __shared__ float red[4];
  if ((threadIdx.x & 31) == 0) red[threadIdx.x>>5] = s;
  __syncthreads();
  if (threadIdx.x == 0){
    float tot = red[0]+red[1]+red[2]+red[3] + Vb[0];
    out[b] = 1.f/(1.f + expf(-tot));
  }
}

extern "C" void kernel_launch(void* const* d_in, const int* in_sizes, int n_in,
                              void* d_out, int out_size){
  (void)in_sizes; (void)n_in; (void)out_size;
  const int*   x   = (const int*)d_in[0];
  const float* emb = (const float*)d_in[1];
  const float* Ww  = (const float*)d_in[2];
  const float* Wb  = (const float*)d_in[3];
  const float* Uw  = (const float*)d_in[4];
  const float* Ubv = (const float*)d_in[5];
  const float* Vw  = (const float*)d_in[6];
  const float* Vb  = (const float*)d_in[7];
  float* out = (float*)d_out;

  static bool attr_done = false;
  if (!attr_done){
    cudaFuncSetAttribute(k_scan, cudaFuncAttributeMaxDynamicSharedMemorySize, SMEM_WORDS*4);
    attr_done = true;
  }

  k_init<<<1024, 256>>>();
  k_pre<<<dim3(HH/64, TOK/64), 256>>>(x, emb, Ww, Wb);
  k_scan<<<dim3(32, 4), 256, SMEM_WORDS*4>>>(Uw, Ubv);
  k_final<<<BB, 128>>>(Vw, Vb, out);
}

// round 10
// speedup vs baseline: 1.2428x; 1.1197x over previous
#include <cuda_runtime.h>
#include <cuda_bf16.h>
#include <cstdint>

#define BB 128
#define SS 512
#define EE 512
#define HH 1024
#define TOK (BB*SS)
#define NCTA 128

// Scratch (allocation-free rule: __device__ globals)
__device__ float g_pre[(size_t)TOK * HH];        // [s*B + b][h], fp32
__device__ float g_h[BB * HH];                   // final hidden state
// packed A fragments: [buf][mgroup][hi/lo][g(64 k16-groups)][wm][lane*4+word] bf16x2 words
__device__ __align__(16) unsigned g_ha[2][4][2][64][2][128];
__device__ unsigned g_arrive[NCTA];              // per-CTA monotonic barrier flags

__device__ __forceinline__ unsigned f2tf(float f){
  unsigned u; asm("cvt.rna.tf32.f32 %0, %1;" : "=r"(u) : "f"(f)); return u;
}
__device__ __forceinline__ void mma8(float c[4], unsigned a0,unsigned a1,unsigned a2,unsigned a3,
                                     unsigned b0,unsigned b1){
  asm volatile("mma.sync.aligned.m16n8k8.row.col.f32.tf32.tf32.f32 "
    "{%0,%1,%2,%3}, {%4,%5,%6,%7}, {%8,%9}, {%0,%1,%2,%3};"
    : "+f"(c[0]),"+f"(c[1]),"+f"(c[2]),"+f"(c[3])
    : "r"(a0),"r"(a1),"r"(a2),"r"(a3),"r"(b0),"r"(b1));
}
__device__ __forceinline__ void mma16(float c[4], uint4 a, uint2 b){
  asm volatile("mma.sync.aligned.m16n8k16.row.col.f32.bf16.bf16.f32 "
    "{%0,%1,%2,%3}, {%4,%5,%6,%7}, {%8,%9}, {%0,%1,%2,%3};"
    : "+f"(c[0]),"+f"(c[1]),"+f"(c[2]),"+f"(c[3])
    : "r"(a.x),"r"(a.y),"r"(a.z),"r"(a.w),"r"(b.x),"r"(b.y));
}
__device__ __forceinline__ unsigned bpack(float x, float y){
  __nv_bfloat16 bx = __float2bfloat16_rn(x), by = __float2bfloat16_rn(y);
  return (unsigned)__bfloat16_as_ushort(bx) | ((unsigned)__bfloat16_as_ushort(by) << 16);
}

__global__ void k_init(){
  int i = blockIdx.x*blockDim.x + threadIdx.x;
  // zero packed-A buffer 0 (h0 = 0): 4*2*64*2*128 = 131072 words = 32768 uint4
  if (i < 32768) ((uint4*)g_ha)[i] = make_uint4(0,0,0,0);
  if (i < NCTA) g_arrive[i] = 0u;
}

// pre[s*B+b][h] = dot(emb[x[b][s]], W[h]) + Wb[h]   (M=65536, N=1024, K=512) -- proven
__global__ __launch_bounds__(256) void k_pre(const int* __restrict__ x, const float* __restrict__ emb,
                                             const float* __restrict__ Ww, const float* __restrict__ Wb){
  __shared__ unsigned As[64][33];
  __shared__ unsigned Bsm[64][33];
  __shared__ const float* rowp[64];
  const int tid = threadIdx.x;
  const int m0 = blockIdx.y*64, n0 = blockIdx.x*64;
  if (tid < 64){
    int tok = m0 + tid;
    int b = tok & (BB-1), s = tok >> 7;
    rowp[tid] = emb + (size_t)x[b*SS + s]*EE;
  }
  __syncthreads();
  const int lane = tid & 31, wid = tid >> 5;
  const int wm = wid >> 1, wn = wid & 1;
  const int gr = lane >> 2, gq = lane & 3;
  float acc[4][4];
  #pragma unroll
  for (int i=0;i<4;i++){ acc[i][0]=0.f; acc[i][1]=0.f; acc[i][2]=0.f; acc[i][3]=0.f; }

  for (int kt = 0; kt < EE/32; ++kt){
    const int k0 = kt*32;
    #pragma unroll
    for (int it=0; it<2; ++it){
      int id = tid + it*256;
      int r = id >> 3, c4 = (id & 7)*4;
      float4 v = *(const float4*)(rowp[r] + k0 + c4);
      As[r][c4+0]=f2tf(v.x); As[r][c4+1]=f2tf(v.y); As[r][c4+2]=f2tf(v.z); As[r][c4+3]=f2tf(v.w);
      float4 w = *(const float4*)(Ww + (size_t)(n0+r)*EE + k0 + c4);
      Bsm[r][c4+0]=f2tf(w.x); Bsm[r][c4+1]=f2tf(w.y); Bsm[r][c4+2]=f2tf(w.z); Bsm[r][c4+3]=f2tf(w.w);
    }
    __syncthreads();
    #pragma unroll
    for (int kk=0; kk<4; ++kk){
      unsigned a0 = As[wm*16+gr  ][kk*8+gq];
      unsigned a1 = As[wm*16+gr+8][kk*8+gq];
      unsigned a2 = As[wm*16+gr  ][kk*8+gq+4];
      unsigned a3 = As[wm*16+gr+8][kk*8+gq+4];
      #pragma unroll
      for (int nf=0; nf<4; ++nf){
        int nr = wn*32 + nf*8 + gr;
        mma8(acc[nf], a0,a1,a2,a3, Bsm[nr][kk*8+gq], Bsm[nr][kk*8+gq+4]);
      }
    }
    __syncthreads();
  }
  #pragma unroll
  for (int nf=0; nf<4; ++nf){
    int nc = n0 + wn*32 + nf*8 + 2*gq;
    int mr = m0 + wm*16 + gr;
    float wb0 = Wb[nc], wb1 = Wb[nc+1];
    g_pre[(size_t)mr*HH + nc]        = acc[nf][0] + wb0;
    g_pre[(size_t)mr*HH + nc + 1]    = acc[nf][1] + wb1;
    g_pre[(size_t)(mr+8)*HH + nc]    = acc[nf][2] + wb0;
    g_pre[(size_t)(mr+8)*HH + nc+1]  = acc[nf][3] + wb1;
  }
}

// ---------------- persistent recurrence: bf16 3-term mma.m16n8k16 ----------------
// 128 CTAs = 4 (M, 32 rows) x 32 (N, 32 cols), 1/SM, 256 threads, 8 warps.
// Warps: wm = wid&1 (m-half), wn = wid>>2? no: wn = wid>>1 (0..3, n-block of 8).
// Warp tile m16 x n8, all K. D += Ahi*Bhi + Ahi*Blo + Alo*Bhi (bf16 split).
// A packed by producer into g_ha fragments; B (U) resident in SMEM bf16 hi/lo.
// SMEM bytes: BpH [0,65536) ; BpL [65536,131072) ; A dbuf [131072,163840)
//             ([2 buf][2 hl][2048 words]) ; Ub [163840,163968)
#define SM_BH 0
#define SM_BL 65536
#define SM_A  131072
#define SM_UB 163840
#define SMEM_BYTES 164096

__device__ __forceinline__ void cpa16(unsigned* dst_sm, const unsigned* src){
  uint32_t sa = (uint32_t)__cvta_generic_to_shared(dst_sm);
  asm volatile("cp.async.cg.shared.global [%0], [%1], 16;" :: "r"(sa), "l"(src));
}

__global__ __launch_bounds__(256, 1) void k_scan(const float* __restrict__ U, const float* __restrict__ Ub){
  extern __shared__ unsigned smw[];   // word-addressed
  const int tid = threadIdx.x, lane = tid & 31, wid = tid >> 5;
  const int gr = lane >> 2, gq = lane & 3;
  const int wm = wid & 1, wn = wid >> 1;        // 2 m-halves x 4 n-blocks of 8
  const int bx = blockIdx.x, by = blockIdx.y;
  const int m0 = by*32, n0 = bx*32;
  const int cta = by*32 + bx;

  // ---- pack U slice (rows n0..n0+31, full K) into bf16 hi/lo B-fragments ----
  // word (g, nf, lane): w0 = U[n0+nf*8+gr][g*16+2gq, +1], w1 = [..+8, ..+9]
  for (int e = tid; e < 64*4*32; e += 256){
    int ln = e & 31, nf = (e >> 5) & 3, g = e >> 7;
    int rr = ln >> 2, qq = ln & 3;
    const float* ur = U + (size_t)(n0 + nf*8 + rr)*HH + g*16 + 2*qq;
    float v0 = ur[0], v1 = ur[1], v2 = ur[8], v3 = ur[9];
    __nv_bfloat16 h0 = __float2bfloat16_rn(v0), h1 = __float2bfloat16_rn(v1);
    __nv_bfloat16 h2 = __float2bfloat16_rn(v2), h3 = __float2bfloat16_rn(v3);
    unsigned w0h = (unsigned)__bfloat16_as_ushort(h0) | ((unsigned)__bfloat16_as_ushort(h1) << 16);
    unsigned w1h = (unsigned)__bfloat16_as_ushort(h2) | ((unsigned)__bfloat16_as_ushort(h3) << 16);
    unsigned w0l = bpack(v0 - __bfloat162float(h0), v1 - __bfloat162float(h1));
    unsigned w1l = bpack(v2 - __bfloat162float(h2), v3 - __bfloat162float(h3));
    unsigned off = (unsigned)(((g*4 + nf)*32 + ln)*2);
    *(uint2*)(smw + SM_BH/4 + off) = make_uint2(w0h, w1h);
    *(uint2*)(smw + SM_BL/4 + off) = make_uint2(w0l, w1l);
  }
  if (tid < 32) ((float*)(smw + SM_UB/4))[tid] = Ub[n0 + tid];

  // epilogue / producer constants
  const int nc = n0 + wn*8 + 2*gq;              // output columns nc, nc+1
  const int mr = m0 + wm*16 + gr;               // output rows mr, mr+8
  const float ub0 = ((float*)0 == 0) ? 0.f : 0.f;  // placeholder removed below
  const float u_b0 = Ub[nc], u_b1 = Ub[nc+1];
  const int gA = bx*2 + (wn >> 1);              // destination k16-group of columns nc
  const int wbase = (wn & 1)*2;                 // a0/a1 vs a2/a3
  const int lslot = (gr*4 + gq)*4 + wbase;      // word index within [lane*4+word]
  __syncthreads();

  for (int t = 0; t < SS; ++t){
    const unsigned* haH = &g_ha[t & 1][by][0][0][0][0];   // 64 g x 2 wm x 128 words
    const unsigned* haL = &g_ha[t & 1][by][1][0][0][0];
    const float* __restrict__ pre = g_pre + (size_t)t*BB*HH;

    // prefetch chunk 0: g 0..7, hi then lo (2048 words each)
    #pragma unroll
    for (int i=0;i<2;++i){
      int idx = (tid + i*256)*4;
      cpa16(smw + SM_A/4 + idx, haH + idx);
      cpa16(smw + SM_A/4 + 2048 + idx, haL + idx);
    }
    asm volatile("cp.async.commit_group;");

    const float pv0 = pre[(size_t)mr*HH + nc];
    const float pv1 = pre[(size_t)mr*HH + nc + 1];
    const float pv2 = pre[(size_t)(mr+8)*HH + nc];
    const float pv3 = pre[(size_t)(mr+8)*HH + nc + 1];

    float accH[2][4], accX[2][4];
    #pragma unroll
    for (int i=0;i<2;++i){
      accH[i][0]=0.f;accH[i][1]=0.f;accH[i][2]=0.f;accH[i][3]=0.f;
      accX[i][0]=0.f;accX[i][1]=0.f;accX[i][2]=0.f;accX[i][3]=0.f;
    }

    #pragma unroll 1
    for (int c = 0; c < 8; ++c){
      if (c < 7){
        unsigned* dst = smw + SM_A/4 + ((c+1)&1)*4096;
        const unsigned* sH = haH + (c+1)*2048;
        const unsigned* sL = haL + (c+1)*2048;
        #pragma unroll
        for (int i=0;i<2;++i){
          int idx = (tid + i*256)*4;
          cpa16(dst + idx, sH + idx);
          cpa16(dst + 2048 + idx, sL + idx);
        }
        asm volatile("cp.async.commit_group;");
        asm volatile("cp.async.wait_group 1;" ::: "memory");
      } else {
        asm volatile("cp.async.wait_group 0;" ::: "memory");
      }
      __syncthreads();   // A[c&1] ready

      const unsigned* ap = smw + SM_A/4 + (c&1)*4096;
      #pragma unroll
      for (int gl = 0; gl < 8; ++gl){
        unsigned aoff = (unsigned)(((gl*2 + wm)*32 + lane)*4);
        uint4 ah = *(const uint4*)(ap + aoff);
        uint4 al = *(const uint4*)(ap + 2048 + aoff);
        unsigned boff = (unsigned)((((c*8+gl)*4 + wn)*32 + lane)*2);
        uint2 bh = *(const uint2*)(smw + SM_BH/4 + boff);
        uint2 bl = *(const uint2*)(smw + SM_BL/4 + boff);
        mma16(accH[gl & 1], ah, bh);
        mma16(accX[gl & 1], ah, bl);
        mma16(accX[gl & 1], al, bh);
      }
      __syncthreads();   // done with A[c&1] before refill
    }

    // epilogue
    float s0 = (accH[0][0]+accH[1][0]) + (accX[0][0]+accX[1][0]);
    float s1 = (accH[0][1]+accH[1][1]) + (accX[0][1]+accX[1][1]);
    float s2 = (accH[0][2]+accH[1][2]) + (accX[0][2]+accX[1][2]);
    float s3 = (accH[0][3]+accH[1][3]) + (accX[0][3]+accX[1][3]);
    float o00 = tanhf(s0 + pv0 + u_b0);   // (mr,   nc)
    float o01 = tanhf(s1 + pv1 + u_b1);   // (mr,   nc+1)
    float o10 = tanhf(s2 + pv2 + u_b0);   // (mr+8, nc)
    float o11 = tanhf(s3 + pv3 + u_b1);   // (mr+8, nc+1)

    if (t < SS-1){
      const int nb = (t & 1) ^ 1;
      __nv_bfloat16 b00 = __float2bfloat16_rn(o00), b01 = __float2bfloat16_rn(o01);
      __nv_bfloat16 b10 = __float2bfloat16_rn(o10), b11 = __float2bfloat16_rn(o11);
      unsigned hi0 = (unsigned)__bfloat16_as_ushort(b00) | ((unsigned)__bfloat16_as_ushort(b01) << 16);
      unsigned hi1 = (unsigned)__bfloat16_as_ushort(b10) | ((unsigned)__bfloat16_as_ushort(b11) << 16);
      unsigned lo0 = bpack(o00 - __bfloat162float(b00), o01 - __bfloat162float(b01));
      unsigned lo1 = bpack(o10 - __bfloat162float(b10), o11 - __bfloat162float(b11));
      *(uint2*)(&g_ha[nb][by][0][gA][wm][lslot]) = make_uint2(hi0, hi1);
      *(uint2*)(&g_ha[nb][by][1][gA][wm][lslot]) = make_uint2(lo0, lo1);
    } else {
      g_h[(size_t)mr*HH + nc]       = o00;
      g_h[(size_t)mr*HH + nc + 1]   = o01;
      g_h[(size_t)(mr+8)*HH + nc]   = o10;
      g_h[(size_t)(mr+8)*HH + nc+1] = o11;
    }

    // distributed flag barrier across 128 CTAs (proven)
    if (t < SS-1){
      __threadfence();
      __syncthreads();
      if (tid == 0) *((volatile unsigned*)&g_arrive[cta]) = (unsigned)(t+1);
      if (tid < NCTA){
        volatile unsigned* f = &g_arrive[tid];
        while (*f <= (unsigned)t) { }
      }
      __syncthreads();
      __threadfence();
    }
    (void)ub0;
  }
}

__global__ void k_final(const float* __restrict__ Vw, const float* __restrict__ Vb, float* __restrict__ out){
  int b = blockIdx.x;
  const float* h = g_h + (size_t)b*HH;
  float s = 0.f;
  for (int k = threadIdx.x; k < HH; k += 128) s += h[k]*Vw[k];
  #pragma unroll
  for (int o=16;o;o>>=1) s += __shfl_down_sync(0xffffffffu, s, o);
  __shared__ float red[4];
  if ((threadIdx.x & 31) == 0) red[threadIdx.x>>5] = s;
  __syncthreads();
  if (threadIdx.x == 0){
    float tot = red[0]+red[1]+red[2]+red[3] + Vb[0];
    out[b] = 1.f/(1.f + expf(-tot));
  }
}

extern "C" void kernel_launch(void* const* d_in, const int* in_sizes, int n_in,
                              void* d_out, int out_size){
  (void)in_sizes; (void)n_in; (void)out_size;
  const int*   x   = (const int*)d_in[0];
  const float* emb = (const float*)d_in[1];
  const float* Ww  = (const float*)d_in[2];
  const float* Wb  = (const float*)d_in[3];
  const float* Uw  = (const float*)d_in[4];
  const float* Ubv = (const float*)d_in[5];
  const float* Vw  = (const float*)d_in[6];
  const float* Vb  = (const float*)d_in[7];
  float* out = (float*)d_out;

  static bool attr_done = false;
  if (!attr_done){
    cudaFuncSetAttribute(k_scan, cudaFuncAttributeMaxDynamicSharedMemorySize, SMEM_BYTES);
    attr_done = true;
  }

  k_init<<<256, 256>>>();
  k_pre<<<dim3(HH/64, TOK/64), 256>>>(x, emb, Ww, Wb);
  k_scan<<<dim3(32, 4), 256, SMEM_BYTES>>>(Uw, Ubv);
  k_final<<<BB, 128>>>(Vw, Vb, out);
}

// round 11
// speedup vs baseline: 1.5424x; 1.2411x over previous
#include <cuda_runtime.h>
#include <cuda_bf16.h>
#include <cstdint>

#define BB 128
#define SS 512
#define EE 512
#define HH 1024
#define TOK (BB*SS)

// Scratch (allocation-free rule: __device__ globals)
__device__ float g_pre[(size_t)TOK * HH];        // [s*B + b][h], fp32
__device__ float g_h[BB * HH];                   // final hidden state
// packed A fragments: [buf][mgroup][hi/lo][g(64 k16-groups)][wm][lane*4+word] bf16x2 words
__device__ __align__(16) unsigned g_ha[2][4][2][64][2][128];
// per-(mgroup, chunk) monotonic write counters, padded to 128B lines
__device__ unsigned g_wc[4][8][32];

__device__ __forceinline__ unsigned f2tf(float f){
  unsigned u; asm("cvt.rna.tf32.f32 %0, %1;" : "=r"(u) : "f"(f)); return u;
}
__device__ __forceinline__ void mma8(float c[4], unsigned a0,unsigned a1,unsigned a2,unsigned a3,
                                     unsigned b0,unsigned b1){
  asm volatile("mma.sync.aligned.m16n8k8.row.col.f32.tf32.tf32.f32 "
    "{%0,%1,%2,%3}, {%4,%5,%6,%7}, {%8,%9}, {%0,%1,%2,%3};"
    : "+f"(c[0]),"+f"(c[1]),"+f"(c[2]),"+f"(c[3])
    : "r"(a0),"r"(a1),"r"(a2),"r"(a3),"r"(b0),"r"(b1));
}
__device__ __forceinline__ void mma16(float c[4], uint4 a, uint2 b){
  asm volatile("mma.sync.aligned.m16n8k16.row.col.f32.bf16.bf16.f32 "
    "{%0,%1,%2,%3}, {%4,%5,%6,%7}, {%8,%9}, {%0,%1,%2,%3};"
    : "+f"(c[0]),"+f"(c[1]),"+f"(c[2]),"+f"(c[3])
    : "r"(a.x),"r"(a.y),"r"(a.z),"r"(a.w),"r"(b.x),"r"(b.y));
}
__device__ __forceinline__ unsigned bpack(float x, float y){
  __nv_bfloat16 bx = __float2bfloat16_rn(x), by = __float2bfloat16_rn(y);
  return (unsigned)__bfloat16_as_ushort(bx) | ((unsigned)__bfloat16_as_ushort(by) << 16);
}
__device__ __forceinline__ void waitflag(const unsigned* p, unsigned tgt){
  unsigned v;
  do { asm volatile("ld.global.acquire.gpu.u32 %0, [%1];" : "=r"(v) : "l"(p) : "memory"); } while (v < tgt);
}

__global__ void k_init(){
  int i = blockIdx.x*blockDim.x + threadIdx.x;
  // zero packed-A buffer 0 (h0 = 0): 4*2*64*2*128 = 131072 words = 32768 uint4
  if (i < 32768) ((uint4*)g_ha)[i] = make_uint4(0,0,0,0);
  if (i < 4*8*32) ((unsigned*)g_wc)[i] = 0u;
}

// pre[s*B+b][h] = dot(emb[x[b][s]], W[h]) + Wb[h]   (M=65536, N=1024, K=512) -- proven
__global__ __launch_bounds__(256) void k_pre(const int* __restrict__ x, const float* __restrict__ emb,
                                             const float* __restrict__ Ww, const float* __restrict__ Wb){
  __shared__ unsigned As[64][33];
  __shared__ unsigned Bsm[64][33];
  __shared__ const float* rowp[64];
  const int tid = threadIdx.x;
  const int m0 = blockIdx.y*64, n0 = blockIdx.x*64;
  if (tid < 64){
    int tok = m0 + tid;
    int b = tok & (BB-1), s = tok >> 7;
    rowp[tid] = emb + (size_t)x[b*SS + s]*EE;
  }
  __syncthreads();
  const int lane = tid & 31, wid = tid >> 5;
  const int wm = wid >> 1, wn = wid & 1;
  const int gr = lane >> 2, gq = lane & 3;
  float acc[4][4];
  #pragma unroll
  for (int i=0;i<4;i++){ acc[i][0]=0.f; acc[i][1]=0.f; acc[i][2]=0.f; acc[i][3]=0.f; }

  for (int kt = 0; kt < EE/32; ++kt){
    const int k0 = kt*32;
    #pragma unroll
    for (int it=0; it<2; ++it){
      int id = tid + it*256;
      int r = id >> 3, c4 = (id & 7)*4;
      float4 v = *(const float4*)(rowp[r] + k0 + c4);
      As[r][c4+0]=f2tf(v.x); As[r][c4+1]=f2tf(v.y); As[r][c4+2]=f2tf(v.z); As[r][c4+3]=f2tf(v.w);
      float4 w = *(const float4*)(Ww + (size_t)(n0+r)*EE + k0 + c4);
      Bsm[r][c4+0]=f2tf(w.x); Bsm[r][c4+1]=f2tf(w.y); Bsm[r][c4+2]=f2tf(w.z); Bsm[r][c4+3]=f2tf(w.w);
    }
    __syncthreads();
    #pragma unroll
    for (int kk=0; kk<4; ++kk){
      unsigned a0 = As[wm*16+gr  ][kk*8+gq];
      unsigned a1 = As[wm*16+gr+8][kk*8+gq];
      unsigned a2 = As[wm*16+gr  ][kk*8+gq+4];
      unsigned a3 = As[wm*16+gr+8][kk*8+gq+4];
      #pragma unroll
      for (int nf=0; nf<4; ++nf){
        int nr = wn*32 + nf*8 + gr;
        mma8(acc[nf], a0,a1,a2,a3, Bsm[nr][kk*8+gq], Bsm[nr][kk*8+gq+4]);
      }
    }
    __syncthreads();
  }
  #pragma unroll
  for (int nf=0; nf<4; ++nf){
    int nc = n0 + wn*32 + nf*8 + 2*gq;
    int mr = m0 + wm*16 + gr;
    float wb0 = Wb[nc], wb1 = Wb[nc+1];
    g_pre[(size_t)mr*HH + nc]        = acc[nf][0] + wb0;
    g_pre[(size_t)mr*HH + nc + 1]    = acc[nf][1] + wb1;
    g_pre[(size_t)(mr+8)*HH + nc]    = acc[nf][2] + wb0;
    g_pre[(size_t)(mr+8)*HH + nc+1]  = acc[nf][3] + wb1;
  }
}

// ---------------- persistent recurrence: bf16 3-term, flag-pipelined ----------------
// 128 CTAs = 4 independent mgroups (by) x 32 n-slices (bx). 256 threads, 8 warps.
// No global barrier: per-(by, chunk) monotonic write counters gate chunk fetches.
// A triple-buffered (16KB/chunk), prefetch distance 2.
#define SM_BH 0
#define SM_BL 65536
#define SM_A  131072
#define SM_UB 180224
#define SMEM_BYTES 180352

__device__ __forceinline__ void cpa16(unsigned* dst_sm, const unsigned* src){
  uint32_t sa = (uint32_t)__cvta_generic_to_shared(dst_sm);
  asm volatile("cp.async.cg.shared.global [%0], [%1], 16;" :: "r"(sa), "l"(src));
}

__global__ __launch_bounds__(256, 1) void k_scan(const float* __restrict__ U, const float* __restrict__ Ub){
  extern __shared__ unsigned smw[];   // word-addressed
  const int tid = threadIdx.x, lane = tid & 31, wid = tid >> 5;
  const int gr = lane >> 2, gq = lane & 3;
  const int wm = wid & 1, wn = wid >> 1;        // 2 m-halves x 4 n-blocks of 8
  const int bx = blockIdx.x, by = blockIdx.y;
  const int n0 = bx*32, m0 = by*32;

  // ---- pack U slice (rows n0..n0+31, full K) into bf16 hi/lo B-fragments ----
  for (int e = tid; e < 64*4*32; e += 256){
    int ln = e & 31, nf = (e >> 5) & 3, g = e >> 7;
    int rr = ln >> 2, qq = ln & 3;
    const float* ur = U + (size_t)(n0 + nf*8 + rr)*HH + g*16 + 2*qq;
    float v0 = ur[0], v1 = ur[1], v2 = ur[8], v3 = ur[9];
    __nv_bfloat16 h0 = __float2bfloat16_rn(v0), h1 = __float2bfloat16_rn(v1);
    __nv_bfloat16 h2 = __float2bfloat16_rn(v2), h3 = __float2bfloat16_rn(v3);
    unsigned w0h = (unsigned)__bfloat16_as_ushort(h0) | ((unsigned)__bfloat16_as_ushort(h1) << 16);
    unsigned w1h = (unsigned)__bfloat16_as_ushort(h2) | ((unsigned)__bfloat16_as_ushort(h3) << 16);
    unsigned w0l = bpack(v0 - __bfloat162float(h0), v1 - __bfloat162float(h1));
    unsigned w1l = bpack(v2 - __bfloat162float(h2), v3 - __bfloat162float(h3));
    unsigned off = (unsigned)(((g*4 + nf)*32 + ln)*2);
    *(uint2*)(smw + SM_BH/4 + off) = make_uint2(w0h, w1h);
    *(uint2*)(smw + SM_BL/4 + off) = make_uint2(w0l, w1l);
  }
  if (tid < 32) ((float*)(smw + SM_UB/4))[tid] = Ub[n0 + tid];

  // epilogue / producer constants
  const int nc = n0 + wn*8 + 2*gq;              // output columns nc, nc+1
  const int mr = m0 + wm*16 + gr;               // output rows mr, mr+8
  const float u_b0 = Ub[nc], u_b1 = Ub[nc+1];
  const int gA = bx*2 + (wn >> 1);              // destination k16-group of columns nc
  const int wbase = (wn & 1)*2;
  const int lslot = (gr*4 + gq)*4 + wbase;
  const int c_w = bx >> 2;                      // this CTA's write chunk
  __syncthreads();

  for (int t = 0; t < SS; ++t){
    const unsigned* haH = &g_ha[t & 1][by][0][0][0][0];
    const unsigned* haL = &g_ha[t & 1][by][1][0][0][0];
    const float* __restrict__ pre = g_pre + (size_t)t*BB*HH;
    const unsigned tgt = 4u*(unsigned)t;

    // gate + prefetch chunks 0,1
    if (tid == 0){ waitflag(&g_wc[by][0][0], tgt); waitflag(&g_wc[by][1][0], tgt); }
    __syncthreads();
    #pragma unroll
    for (int p = 0; p < 2; ++p){
      unsigned* dst = smw + SM_A/4 + p*4096;
      #pragma unroll
      for (int i=0;i<2;++i){
        int idx = (tid + i*256)*4;
        cpa16(dst + idx, haH + p*2048 + idx);
        cpa16(dst + 2048 + idx, haL + p*2048 + idx);
      }
      asm volatile("cp.async.commit_group;");
    }

    const float pv0 = pre[(size_t)mr*HH + nc];
    const float pv1 = pre[(size_t)mr*HH + nc + 1];
    const float pv2 = pre[(size_t)(mr+8)*HH + nc];
    const float pv3 = pre[(size_t)(mr+8)*HH + nc + 1];

    float accH[2][4], accX[2][4];
    #pragma unroll
    for (int i=0;i<2;++i){
      accH[i][0]=0.f;accH[i][1]=0.f;accH[i][2]=0.f;accH[i][3]=0.f;
      accX[i][0]=0.f;accX[i][1]=0.f;accX[i][2]=0.f;accX[i][3]=0.f;
    }

    #pragma unroll 1
    for (int c = 0; c < 8; ++c){
      if (c < 7) asm volatile("cp.async.wait_group 1;" ::: "memory");
      else       asm volatile("cp.async.wait_group 0;" ::: "memory");
      if (tid == 0 && c+2 < 8) waitflag(&g_wc[by][c+2][0], tgt);
      __syncthreads();   // buf c%3 ready; prev mma done; flag c+2 observed

      if (c+2 < 8){
        unsigned* dst = smw + SM_A/4 + ((c+2)%3)*4096;
        const unsigned* sH = haH + (c+2)*2048;
        const unsigned* sL = haL + (c+2)*2048;
        #pragma unroll
        for (int i=0;i<2;++i){
          int idx = (tid + i*256)*4;
          cpa16(dst + idx, sH + idx);
          cpa16(dst + 2048 + idx, sL + idx);
        }
        asm volatile("cp.async.commit_group;");
      }

      const unsigned* ap = smw + SM_A/4 + (c%3)*4096;
      #pragma unroll
      for (int gl = 0; gl < 8; ++gl){
        unsigned aoff = (unsigned)(((gl*2 + wm)*32 + lane)*4);
        uint4 ah = *(const uint4*)(ap + aoff);
        uint4 al = *(const uint4*)(ap + 2048 + aoff);
        unsigned boff = (unsigned)((((c*8+gl)*4 + wn)*32 + lane)*2);
        uint2 bh = *(const uint2*)(smw + SM_BH/4 + boff);
        uint2 bl = *(const uint2*)(smw + SM_BL/4 + boff);
        mma16(accH[gl & 1], ah, bh);
        mma16(accX[gl & 1], ah, bl);
        mma16(accX[gl & 1], al, bh);
      }
    }

    // epilogue
    float s0 = (accH[0][0]+accH[1][0]) + (accX[0][0]+accX[1][0]);
    float s1 = (accH[0][1]+accH[1][1]) + (accX[0][1]+accX[1][1]);
    float s2 = (accH[0][2]+accH[1][2]) + (accX[0][2]+accX[1][2]);
    float s3 = (accH[0][3]+accH[1][3]) + (accX[0][3]+accX[1][3]);
    float o00 = tanhf(s0 + pv0 + u_b0);
    float o01 = tanhf(s1 + pv1 + u_b1);
    float o10 = tanhf(s2 + pv2 + u_b0);
    float o11 = tanhf(s3 + pv3 + u_b1);

    if (t < SS-1){
      const int nb = (t & 1) ^ 1;
      __nv_bfloat16 b00 = __float2bfloat16_rn(o00), b01 = __float2bfloat16_rn(o01);
      __nv_bfloat16 b10 = __float2bfloat16_rn(o10), b11 = __float2bfloat16_rn(o11);
      unsigned hi0 = (unsigned)__bfloat16_as_ushort(b00) | ((unsigned)__bfloat16_as_ushort(b01) << 16);
      unsigned hi1 = (unsigned)__bfloat16_as_ushort(b10) | ((unsigned)__bfloat16_as_ushort(b11) << 16);
      unsigned lo0 = bpack(o00 - __bfloat162float(b00), o01 - __bfloat162float(b01));
      unsigned lo1 = bpack(o10 - __bfloat162float(b10), o11 - __bfloat162float(b11));
      *(uint2*)(&g_ha[nb][by][0][gA][wm][lslot]) = make_uint2(hi0, hi1);
      *(uint2*)(&g_ha[nb][by][1][gA][wm][lslot]) = make_uint2(lo0, lo1);
      __threadfence();
      __syncthreads();   // all fragment STGs fenced before flag
      if (tid == 0) atomicAdd(&g_wc[by][c_w][0], 1u);
    } else {
      g_h[(size_t)mr*HH + nc]       = o00;
      g_h[(size_t)mr*HH + nc + 1]   = o01;
      g_h[(size_t)(mr+8)*HH + nc]   = o10;
      g_h[(size_t)(mr+8)*HH + nc+1] = o11;
    }
  }
}

__global__ void k_final(const float* __restrict__ Vw, const float* __restrict__ Vb, float* __restrict__ out){
  int b = blockIdx.x;
  const float* h = g_h + (size_t)b*HH;
  float s = 0.f;
  for (int k = threadIdx.x; k < HH; k += 128) s += h[k]*Vw[k];
  #pragma unroll
  for (int o=16;o;o>>=1) s += __shfl_down_sync(0xffffffffu, s, o);
  __shared__ float red[4];
  if ((threadIdx.x & 31) == 0) red[threadIdx.x>>5] = s;
  __syncthreads();
  if (threadIdx.x == 0){
    float tot = red[0]+red[1]+red[2]+red[3] + Vb[0];
    out[b] = 1.f/(1.f + expf(-tot));
  }
}

extern "C" void kernel_launch(void* const* d_in, const int* in_sizes, int n_in,
                              void* d_out, int out_size){
  (void)in_sizes; (void)n_in; (void)out_size;
  const int*   x   = (const int*)d_in[0];
  const float* emb = (const float*)d_in[1];
  const float* Ww  = (const float*)d_in[2];
  const float* Wb  = (const float*)d_in[3];
  const float* Uw  = (const float*)d_in[4];
  const float* Ubv = (const float*)d_in[5];
  const float* Vw  = (const float*)d_in[6];
  const float* Vb  = (const float*)d_in[7];
  float* out = (float*)d_out;

  static bool attr_done = false;
  if (!attr_done){
    cudaFuncSetAttribute(k_scan, cudaFuncAttributeMaxDynamicSharedMemorySize, SMEM_BYTES);
    attr_done = true;
  }

  k_init<<<256, 256>>>();
  k_pre<<<dim3(HH/64, TOK/64), 256>>>(x, emb, Ww, Wb);
  k_scan<<<dim3(32, 4), 256, SMEM_BYTES>>>(Uw, Ubv);
  k_final<<<BB, 128>>>(Vw, Vb, out);
}

// round 12
// speedup vs baseline: 1.7953x; 1.1640x over previous
#include <cuda_runtime.h>
#include <cuda_fp16.h>
#include <cstdint>

#define BB 128
#define SS 512
#define EE 512
#define HH 1024
#define TOK (BB*SS)

// Scratch (allocation-free rule: __device__ globals)
__device__ float g_pre[(size_t)TOK * HH];        // [s*B + b][h], fp32
__device__ float g_h[BB * HH];                   // final hidden state
// packed A fragments (fp16 h): [buf][mgroup][g(64 k16-groups)][wm][lane*4+word] fp16x2 words
__device__ __align__(16) unsigned g_ha[2][4][64][2][128];
// per-(mgroup, chunk) monotonic write counters, padded to 128B lines
__device__ unsigned g_wc[4][8][32];

__device__ __forceinline__ unsigned f2tf(float f){
  unsigned u; asm("cvt.rna.tf32.f32 %0, %1;" : "=r"(u) : "f"(f)); return u;
}
__device__ __forceinline__ void mma8(float c[4], unsigned a0,unsigned a1,unsigned a2,unsigned a3,
                                     unsigned b0,unsigned b1){
  asm volatile("mma.sync.aligned.m16n8k8.row.col.f32.tf32.tf32.f32 "
    "{%0,%1,%2,%3}, {%4,%5,%6,%7}, {%8,%9}, {%0,%1,%2,%3};"
    : "+f"(c[0]),"+f"(c[1]),"+f"(c[2]),"+f"(c[3])
    : "r"(a0),"r"(a1),"r"(a2),"r"(a3),"r"(b0),"r"(b1));
}
__device__ __forceinline__ void mma16h(float c[4], uint4 a, unsigned b0, unsigned b1){
  asm volatile("mma.sync.aligned.m16n8k16.row.col.f32.f16.f16.f32 "
    "{%0,%1,%2,%3}, {%4,%5,%6,%7}, {%8,%9}, {%0,%1,%2,%3};"
    : "+f"(c[0]),"+f"(c[1]),"+f"(c[2]),"+f"(c[3])
    : "r"(a.x),"r"(a.y),"r"(a.z),"r"(a.w),"r"(b0),"r"(b1));
}
__device__ __forceinline__ unsigned hpack(float x, float y){
  return (unsigned)__half_as_ushort(__float2half_rn(x))
       | ((unsigned)__half_as_ushort(__float2half_rn(y)) << 16);
}
__device__ __forceinline__ void waitflag(const unsigned* p, unsigned tgt){
  unsigned v;
  do { asm volatile("ld.global.acquire.gpu.u32 %0, [%1];" : "=r"(v) : "l"(p) : "memory"); } while (v < tgt);
}

__global__ void k_init(){
  int i = blockIdx.x*blockDim.x + threadIdx.x;
  // zero packed-A buffer 0 (h0 = 0): 4*64*2*128 = 65536 words = 16384 uint4
  if (i < 16384) ((uint4*)g_ha)[i] = make_uint4(0,0,0,0);
  if (i < 4*8*32) ((unsigned*)g_wc)[i] = 0u;
}

// pre[s*B+b][h] = dot(emb[x[b][s]], W[h]) + Wb[h]   (M=65536, N=1024, K=512) -- proven
__global__ __launch_bounds__(256) void k_pre(const int* __restrict__ x, const float* __restrict__ emb,
                                             const float* __restrict__ Ww, const float* __restrict__ Wb){
  __shared__ unsigned As[64][33];
  __shared__ unsigned Bsm[64][33];
  __shared__ const float* rowp[64];
  const int tid = threadIdx.x;
  const int m0 = blockIdx.y*64, n0 = blockIdx.x*64;
  if (tid < 64){
    int tok = m0 + tid;
    int b = tok & (BB-1), s = tok >> 7;
    rowp[tid] = emb + (size_t)x[b*SS + s]*EE;
  }
  __syncthreads();
  const int lane = tid & 31, wid = tid >> 5;
  const int wm = wid >> 1, wn = wid & 1;
  const int gr = lane >> 2, gq = lane & 3;
  float acc[4][4];
  #pragma unroll
  for (int i=0;i<4;i++){ acc[i][0]=0.f; acc[i][1]=0.f; acc[i][2]=0.f; acc[i][3]=0.f; }

  for (int kt = 0; kt < EE/32; ++kt){
    const int k0 = kt*32;
    #pragma unroll
    for (int it=0; it<2; ++it){
      int id = tid + it*256;
      int r = id >> 3, c4 = (id & 7)*4;
      float4 v = *(const float4*)(rowp[r] + k0 + c4);
      As[r][c4+0]=f2tf(v.x); As[r][c4+1]=f2tf(v.y); As[r][c4+2]=f2tf(v.z); As[r][c4+3]=f2tf(v.w);
      float4 w = *(const float4*)(Ww + (size_t)(n0+r)*EE + k0 + c4);
      Bsm[r][c4+0]=f2tf(w.x); Bsm[r][c4+1]=f2tf(w.y); Bsm[r][c4+2]=f2tf(w.z); Bsm[r][c4+3]=f2tf(w.w);
    }
    __syncthreads();
    #pragma unroll
    for (int kk=0; kk<4; ++kk){
      unsigned a0 = As[wm*16+gr  ][kk*8+gq];
      unsigned a1 = As[wm*16+gr+8][kk*8+gq];
      unsigned a2 = As[wm*16+gr  ][kk*8+gq+4];
      unsigned a3 = As[wm*16+gr+8][kk*8+gq+4];
      #pragma unroll
      for (int nf=0; nf<4; ++nf){
        int nr = wn*32 + nf*8 + gr;
        mma8(acc[nf], a0,a1,a2,a3, Bsm[nr][kk*8+gq], Bsm[nr][kk*8+gq+4]);
      }
    }
    __syncthreads();
  }
  #pragma unroll
  for (int nf=0; nf<4; ++nf){
    int nc = n0 + wn*32 + nf*8 + 2*gq;
    int mr = m0 + wm*16 + gr;
    float wb0 = Wb[nc], wb1 = Wb[nc+1];
    g_pre[(size_t)mr*HH + nc]        = acc[nf][0] + wb0;
    g_pre[(size_t)mr*HH + nc + 1]    = acc[nf][1] + wb1;
    g_pre[(size_t)(mr+8)*HH + nc]    = acc[nf][2] + wb0;
    g_pre[(size_t)(mr+8)*HH + nc+1]  = acc[nf][3] + wb1;
  }
}

// ---------------- persistent recurrence: fp16 A single + B hi/lo, flag-pipelined ----------------
// 128 CTAs = 4 independent mgroups (by) x 32 n-slices (bx). 256 threads, 8 warps.
// D_H += a*bh ; D_L += a*(4096*bl) ; result = D_H + D_L/4096. 2 HMMA per k16.
// B interleaved (bh0,bh1,bl0,bl1) per lane -> single LDS.128.
// A triple-buffered 8KB chunks, prefetch distance 2, per-(by,chunk) flag gating.
#define SM_B  0
#define SM_A  131072
#define SM_UB 155648
#define SMEM_BYTES 155904
#define LO_SCALE 4096.0f
#define LO_INV   (1.0f/4096.0f)

__device__ __forceinline__ void cpa16(unsigned* dst_sm, const unsigned* src){
  uint32_t sa = (uint32_t)__cvta_generic_to_shared(dst_sm);
  asm volatile("cp.async.cg.shared.global [%0], [%1], 16;" :: "r"(sa), "l"(src));
}

__global__ __launch_bounds__(256, 1) void k_scan(const float* __restrict__ U, const float* __restrict__ Ub){
  extern __shared__ unsigned smw[];   // word-addressed
  const int tid = threadIdx.x, lane = tid & 31, wid = tid >> 5;
  const int gr = lane >> 2, gq = lane & 3;
  const int wm = wid & 1, wn = wid >> 1;        // 2 m-halves x 4 n-blocks of 8
  const int bx = blockIdx.x, by = blockIdx.y;
  const int n0 = bx*32, m0 = by*32;

  // ---- pack U slice (rows n0..n0+31, full K) into fp16 hi + scaled-lo B-fragments ----
  // per lane uint4: (bh_w0, bh_w1, bl_w0, bl_w1); w0 = U[n][g*16+2q,+1], w1 = [..+8,+9]
  for (int e = tid; e < 64*4*32; e += 256){
    int ln = e & 31, nf = (e >> 5) & 3, g = e >> 7;
    int rr = ln >> 2, qq = ln & 3;
    const float* ur = U + (size_t)(n0 + nf*8 + rr)*HH + g*16 + 2*qq;
    float v0 = ur[0], v1 = ur[1], v2 = ur[8], v3 = ur[9];
    float h0 = __half2float(__float2half_rn(v0));
    float h1 = __half2float(__float2half_rn(v1));
    float h2 = __half2float(__float2half_rn(v2));
    float h3 = __half2float(__float2half_rn(v3));
    unsigned bh0 = hpack(v0, v1), bh1 = hpack(v2, v3);
    unsigned bl0 = hpack((v0-h0)*LO_SCALE, (v1-h1)*LO_SCALE);
    unsigned bl1 = hpack((v2-h2)*LO_SCALE, (v3-h3)*LO_SCALE);
    unsigned off = (unsigned)(((g*4 + nf)*32 + ln)*4);
    *(uint4*)(smw + SM_B/4 + off) = make_uint4(bh0, bh1, bl0, bl1);
  }
  if (tid < 32) ((float*)(smw + SM_UB/4))[tid] = Ub[n0 + tid];

  // epilogue / producer constants
  const int nc = n0 + wn*8 + 2*gq;              // output columns nc, nc+1
  const int mr = m0 + wm*16 + gr;               // output rows mr, mr+8
  const float u_b0 = Ub[nc], u_b1 = Ub[nc+1];
  const int gA = bx*2 + (wn >> 1);              // destination k16-group of columns nc
  const int wbase = (wn & 1)*2;
  const int lslot = (gr*4 + gq)*4 + wbase;
  const int c_w = bx >> 2;                      // this CTA's write chunk
  __syncthreads();

  for (int t = 0; t < SS; ++t){
    const unsigned* ha = &g_ha[t & 1][by][0][0][0];   // 64 g x 2 wm x 128 words
    const float* __restrict__ pre = g_pre + (size_t)t*BB*HH;
    const unsigned tgt = 4u*(unsigned)t;

    // gate + prefetch chunks 0,1 (2048 words each)
    if (tid == 0){ waitflag(&g_wc[by][0][0], tgt); waitflag(&g_wc[by][1][0], tgt); }
    __syncthreads();
    #pragma unroll
    for (int p = 0; p < 2; ++p){
      unsigned* dst = smw + SM_A/4 + p*2048;
      #pragma unroll
      for (int i=0;i<2;++i){ int idx = (tid + i*256)*4; cpa16(dst + idx, ha + p*2048 + idx); }
      asm volatile("cp.async.commit_group;");
    }

    const float pv0 = pre[(size_t)mr*HH + nc];
    const float pv1 = pre[(size_t)mr*HH + nc + 1];
    const float pv2 = pre[(size_t)(mr+8)*HH + nc];
    const float pv3 = pre[(size_t)(mr+8)*HH + nc + 1];

    float accH[2][4], accL[2][4];
    #pragma unroll
    for (int i=0;i<2;++i){
      accH[i][0]=0.f;accH[i][1]=0.f;accH[i][2]=0.f;accH[i][3]=0.f;
      accL[i][0]=0.f;accL[i][1]=0.f;accL[i][2]=0.f;accL[i][3]=0.f;
    }

    #pragma unroll 1
    for (int c = 0; c < 8; ++c){
      if (c < 7) asm volatile("cp.async.wait_group 1;" ::: "memory");
      else       asm volatile("cp.async.wait_group 0;" ::: "memory");
      if (tid == 0 && c+2 < 8) waitflag(&g_wc[by][c+2][0], tgt);
      __syncthreads();   // buf c%3 ready; prev mma done; flag c+2 observed

      if (c+2 < 8){
        unsigned* dst = smw + SM_A/4 + ((c+2)%3)*2048;
        const unsigned* src = ha + (c+2)*2048;
        #pragma unroll
        for (int i=0;i<2;++i){ int idx = (tid + i*256)*4; cpa16(dst + idx, src + idx); }
        asm volatile("cp.async.commit_group;");
      }

      const unsigned* ap = smw + SM_A/4 + (c%3)*2048;
      #pragma unroll
      for (int gl = 0; gl < 8; ++gl){
        uint4 a = *(const uint4*)(ap + ((gl*2 + wm)*32 + lane)*4);
        uint4 b = *(const uint4*)(smw + SM_B/4 + (((c*8+gl)*4 + wn)*32 + lane)*4);
        mma16h(accH[gl & 1], a, b.x, b.y);
        mma16h(accL[gl & 1], a, b.z, b.w);
      }
    }

    // epilogue: s = accH + accL/4096
    float s0 = (accH[0][0]+accH[1][0]) + (accL[0][0]+accL[1][0])*LO_INV;
    float s1 = (accH[0][1]+accH[1][1]) + (accL[0][1]+accL[1][1])*LO_INV;
    float s2 = (accH[0][2]+accH[1][2]) + (accL[0][2]+accL[1][2])*LO_INV;
    float s3 = (accH[0][3]+accH[1][3]) + (accL[0][3]+accL[1][3])*LO_INV;
    float o00 = tanhf(s0 + pv0 + u_b0);
    float o01 = tanhf(s1 + pv1 + u_b1);
    float o10 = tanhf(s2 + pv2 + u_b0);
    float o11 = tanhf(s3 + pv3 + u_b1);

    if (t < SS-1){
      const int nb = (t & 1) ^ 1;
      *(uint2*)(&g_ha[nb][by][gA][wm][lslot]) = make_uint2(hpack(o00, o01), hpack(o10, o11));
      __syncthreads();   // all CTA fragment STGs before the release below
      if (tid == 0)
        asm volatile("red.release.gpu.global.add.u32 [%0], %1;"
                     :: "l"(&g_wc[by][c_w][0]), "r"(1u) : "memory");
    } else {
      g_h[(size_t)mr*HH + nc]       = o00;
      g_h[(size_t)mr*HH + nc + 1]   = o01;
      g_h[(size_t)(mr+8)*HH + nc]   = o10;
      g_h[(size_t)(mr+8)*HH + nc+1] = o11;
    }
  }
}

__global__ void k_final(const float* __restrict__ Vw, const float* __restrict__ Vb, float* __restrict__ out){
  int b = blockIdx.x;
  const float* h = g_h + (size_t)b*HH;
  float s = 0.f;
  for (int k = threadIdx.x; k < HH; k += 128) s += h[k]*Vw[k];
  #pragma unroll
  for (int o=16;o;o>>=1) s += __shfl_down_sync(0xffffffffu, s, o);
  __shared__ float red[4];
  if ((threadIdx.x & 31) == 0) red[threadIdx.x>>5] = s;
  __syncthreads();
  if (threadIdx.x == 0){
    float tot = red[0]+red[1]+red[2]+red[3] + Vb[0];
    out[b] = 1.f/(1.f + expf(-tot));
  }
}

extern "C" void kernel_launch(void* const* d_in, const int* in_sizes, int n_in,
                              void* d_out, int out_size){
  (void)in_sizes; (void)n_in; (void)out_size;
  const int*   x   = (const int*)d_in[0];
  const float* emb = (const float*)d_in[1];
  const float* Ww  = (const float*)d_in[2];
  const float* Wb  = (const float*)d_in[3];
  const float* Uw  = (const float*)d_in[4];
  const float* Ubv = (const float*)d_in[5];
  const float* Vw  = (const float*)d_in[6];
  const float* Vb  = (const float*)d_in[7];
  float* out = (float*)d_out;

  static bool attr_done = false;
  if (!attr_done){
    cudaFuncSetAttribute(k_scan, cudaFuncAttributeMaxDynamicSharedMemorySize, SMEM_BYTES);
    attr_done = true;
  }

  k_init<<<256, 256>>>();
  k_pre<<<dim3(HH/64, TOK/64), 256>>>(x, emb, Ww, Wb);
  k_scan<<<dim3(32, 4), 256, SMEM_BYTES>>>(Uw, Ubv);
  k_final<<<BB, 128>>>(Vw, Vb, out);
}

// round 13
// speedup vs baseline: 2.6272x; 1.4634x over previous
#include <cuda_runtime.h>
#include <cuda_fp16.h>
#include <cstdint>

#define BB 128
#define SS 512
#define EE 512
#define HH 1024
#define TOK (BB*SS)

// Scratch (allocation-free rule: __device__ globals)
__device__ float g_pre[(size_t)TOK * HH];        // [s*B + b][h], fp32
__device__ float g_h[BB * HH];                   // final hidden state
// packed A fragments (fp16 h): [buf][mgroup][g(64 k16-groups)][wm][lane*4+word] fp16x2 words
__device__ __align__(16) unsigned g_ha[2][4][64][2][128];
// per-(mgroup, chunk) monotonic write counters, padded to 128B lines
__device__ unsigned g_wc[4][8][32];

__device__ __forceinline__ unsigned f2tf(float f){
  unsigned u; asm("cvt.rna.tf32.f32 %0, %1;" : "=r"(u) : "f"(f)); return u;
}
__device__ __forceinline__ void mma8(float c[4], unsigned a0,unsigned a1,unsigned a2,unsigned a3,
                                     unsigned b0,unsigned b1){
  asm volatile("mma.sync.aligned.m16n8k8.row.col.f32.tf32.tf32.f32 "
    "{%0,%1,%2,%3}, {%4,%5,%6,%7}, {%8,%9}, {%0,%1,%2,%3};"
    : "+f"(c[0]),"+f"(c[1]),"+f"(c[2]),"+f"(c[3])
    : "r"(a0),"r"(a1),"r"(a2),"r"(a3),"r"(b0),"r"(b1));
}
__device__ __forceinline__ void mma16h(float c[4], uint4 a, unsigned b0, unsigned b1){
  asm volatile("mma.sync.aligned.m16n8k16.row.col.f32.f16.f16.f32 "
    "{%0,%1,%2,%3}, {%4,%5,%6,%7}, {%8,%9}, {%0,%1,%2,%3};"
    : "+f"(c[0]),"+f"(c[1]),"+f"(c[2]),"+f"(c[3])
    : "r"(a.x),"r"(a.y),"r"(a.z),"r"(a.w),"r"(b0),"r"(b1));
}
__device__ __forceinline__ unsigned hpack(float x, float y){
  return (unsigned)__half_as_ushort(__float2half_rn(x))
       | ((unsigned)__half_as_ushort(__float2half_rn(y)) << 16);
}
__device__ __forceinline__ void waitflag(const unsigned* p, unsigned tgt){
  unsigned v;
  do { asm volatile("ld.global.acquire.gpu.u32 %0, [%1];" : "=r"(v) : "l"(p) : "memory"); } while (v < tgt);
}

__global__ void k_init(){
  int i = blockIdx.x*blockDim.x + threadIdx.x;
  // zero packed-A buffer 0 (h0 = 0): 4*64*2*128 = 65536 words = 16384 uint4
  if (i < 16384) ((uint4*)g_ha)[i] = make_uint4(0,0,0,0);
  if (i < 4*8*32) ((unsigned*)g_wc)[i] = 0u;
}

// pre[s*B+b][h] = dot(emb[x[b][s]], W[h]) + Wb[h]   (M=65536, N=1024, K=512) -- proven
__global__ __launch_bounds__(256) void k_pre(const int* __restrict__ x, const float* __restrict__ emb,
                                             const float* __restrict__ Ww, const float* __restrict__ Wb){
  __shared__ unsigned As[64][33];
  __shared__ unsigned Bsm[64][33];
  __shared__ const float* rowp[64];
  const int tid = threadIdx.x;
  const int m0 = blockIdx.y*64, n0 = blockIdx.x*64;
  if (tid < 64){
    int tok = m0 + tid;
    int b = tok & (BB-1), s = tok >> 7;
    rowp[tid] = emb + (size_t)x[b*SS + s]*EE;
  }
  __syncthreads();
  const int lane = tid & 31, wid = tid >> 5;
  const int wm = wid >> 1, wn = wid & 1;
  const int gr = lane >> 2, gq = lane & 3;
  float acc[4][4];
  #pragma unroll
  for (int i=0;i<4;i++){ acc[i][0]=0.f; acc[i][1]=0.f; acc[i][2]=0.f; acc[i][3]=0.f; }

  for (int kt = 0; kt < EE/32; ++kt){
    const int k0 = kt*32;
    #pragma unroll
    for (int it=0; it<2; ++it){
      int id = tid + it*256;
      int r = id >> 3, c4 = (id & 7)*4;
      float4 v = *(const float4*)(rowp[r] + k0 + c4);
      As[r][c4+0]=f2tf(v.x); As[r][c4+1]=f2tf(v.y); As[r][c4+2]=f2tf(v.z); As[r][c4+3]=f2tf(v.w);
      float4 w = *(const float4*)(Ww + (size_t)(n0+r)*EE + k0 + c4);
      Bsm[r][c4+0]=f2tf(w.x); Bsm[r][c4+1]=f2tf(w.y); Bsm[r][c4+2]=f2tf(w.z); Bsm[r][c4+3]=f2tf(w.w);
    }
    __syncthreads();
    #pragma unroll
    for (int kk=0; kk<4; ++kk){
      unsigned a0 = As[wm*16+gr  ][kk*8+gq];
      unsigned a1 = As[wm*16+gr+8][kk*8+gq];
      unsigned a2 = As[wm*16+gr  ][kk*8+gq+4];
      unsigned a3 = As[wm*16+gr+8][kk*8+gq+4];
      #pragma unroll
      for (int nf=0; nf<4; ++nf){
        int nr = wn*32 + nf*8 + gr;
        mma8(acc[nf], a0,a1,a2,a3, Bsm[nr][kk*8+gq], Bsm[nr][kk*8+gq+4]);
      }
    }
    __syncthreads();
  }
  #pragma unroll
  for (int nf=0; nf<4; ++nf){
    int nc = n0 + wn*32 + nf*8 + 2*gq;
    int mr = m0 + wm*16 + gr;
    float wb0 = Wb[nc], wb1 = Wb[nc+1];
    g_pre[(size_t)mr*HH + nc]        = acc[nf][0] + wb0;
    g_pre[(size_t)mr*HH + nc + 1]    = acc[nf][1] + wb1;
    g_pre[(size_t)(mr+8)*HH + nc]    = acc[nf][2] + wb0;
    g_pre[(size_t)(mr+8)*HH + nc+1]  = acc[nf][3] + wb1;
  }
}

// ---------------- persistent recurrence: fp16, full-A SMEM, 2 syncs/step ----------------
// 128 CTAs = 4 independent mgroups (by) x 32 n-slices (bx). 256 threads, 8 warps.
// Warp w owns A-chunk w: lane0 polls flag w (8 parallel polls), warp fetches its
// 8KB chunk via cp.async, one __syncthreads, then 64 uninterrupted k16 mma groups.
// D_H += a*bh ; D_L += a*(4096*bl) ; result = D_H + D_L/4096 (R12-proven math).
#define SM_B  0
#define SM_A  131072
#define SM_UB 196608
#define SMEM_BYTES 196736
#define LO_SCALE 4096.0f
#define LO_INV   (1.0f/4096.0f)

__device__ __forceinline__ void cpa16(unsigned* dst_sm, const unsigned* src){
  uint32_t sa = (uint32_t)__cvta_generic_to_shared(dst_sm);
  asm volatile("cp.async.cg.shared.global [%0], [%1], 16;" :: "r"(sa), "l"(src));
}

__global__ __launch_bounds__(256, 1) void k_scan(const float* __restrict__ U, const float* __restrict__ Ub){
  extern __shared__ unsigned smw[];   // word-addressed
  const int tid = threadIdx.x, lane = tid & 31, wid = tid >> 5;
  const int gr = lane >> 2, gq = lane & 3;
  const int wm = wid & 1, wn = wid >> 1;        // 2 m-halves x 4 n-blocks of 8
  const int bx = blockIdx.x, by = blockIdx.y;
  const int n0 = bx*32, m0 = by*32;

  // ---- pack U slice (rows n0..n0+31, full K) into fp16 hi + scaled-lo B-fragments ----
  for (int e = tid; e < 64*4*32; e += 256){
    int ln = e & 31, nf = (e >> 5) & 3, g = e >> 7;
    int rr = ln >> 2, qq = ln & 3;
    const float* ur = U + (size_t)(n0 + nf*8 + rr)*HH + g*16 + 2*qq;
    float v0 = ur[0], v1 = ur[1], v2 = ur[8], v3 = ur[9];
    float h0 = __half2float(__float2half_rn(v0));
    float h1 = __half2float(__float2half_rn(v1));
    float h2 = __half2float(__float2half_rn(v2));
    float h3 = __half2float(__float2half_rn(v3));
    unsigned bh0 = hpack(v0, v1), bh1 = hpack(v2, v3);
    unsigned bl0 = hpack((v0-h0)*LO_SCALE, (v1-h1)*LO_SCALE);
    unsigned bl1 = hpack((v2-h2)*LO_SCALE, (v3-h3)*LO_SCALE);
    unsigned off = (unsigned)(((g*4 + nf)*32 + ln)*4);
    *(uint4*)(smw + SM_B/4 + off) = make_uint4(bh0, bh1, bl0, bl1);
  }
  if (tid < 32) ((float*)(smw + SM_UB/4))[tid] = Ub[n0 + tid];

  // epilogue / producer constants
  const int nc = n0 + wn*8 + 2*gq;              // output columns nc, nc+1
  const int mr = m0 + wm*16 + gr;               // output rows mr, mr+8
  const float u_b0 = Ub[nc], u_b1 = Ub[nc+1];
  const int gA = bx*2 + (wn >> 1);              // destination k16-group of columns nc
  const int wbase = (wn & 1)*2;
  const int lslot = (gr*4 + gq)*4 + wbase;
  const int c_w = bx >> 2;                      // this CTA's write chunk
  __syncthreads();

  for (int t = 0; t < SS; ++t){
    const unsigned* ha = &g_ha[t & 1][by][0][0][0];   // 16384 words
    const float* __restrict__ pre = g_pre + (size_t)t*BB*HH;
    const unsigned tgt = 4u*(unsigned)t;

    // load pre values first (overlaps with poll/fetch below)
    const float pv0 = pre[(size_t)mr*HH + nc];
    const float pv1 = pre[(size_t)mr*HH + nc + 1];
    const float pv2 = pre[(size_t)(mr+8)*HH + nc];
    const float pv3 = pre[(size_t)(mr+8)*HH + nc + 1];

    // warp wid: gate + fetch its own chunk (2048 words = 8KB), all warps parallel
    if (lane == 0) waitflag(&g_wc[by][wid][0], tgt);
    __syncwarp();
    {
      const unsigned* src = ha + wid*2048;
      unsigned* dst = smw + SM_A/4 + wid*2048;
      #pragma unroll
      for (int i=0;i<16;++i){ int idx = (lane + i*32)*4; cpa16(dst + idx, src + idx); }
      asm volatile("cp.async.commit_group;");
      asm volatile("cp.async.wait_group 0;" ::: "memory");
    }
    __syncthreads();   // all chunks resident + visible CTA-wide

    float accH[2][4], accL[2][4];
    #pragma unroll
    for (int i=0;i<2;++i){
      accH[i][0]=0.f;accH[i][1]=0.f;accH[i][2]=0.f;accH[i][3]=0.f;
      accL[i][0]=0.f;accL[i][1]=0.f;accL[i][2]=0.f;accL[i][3]=0.f;
    }

    // 64 uninterrupted k16 groups
    const unsigned* ap = smw + SM_A/4;
    const unsigned* bp = smw + SM_B/4;
    #pragma unroll 16
    for (int g = 0; g < 64; ++g){
      uint4 a = *(const uint4*)(ap + ((g*2 + wm)*32 + lane)*4);
      uint4 b = *(const uint4*)(bp + ((g*4 + wn)*32 + lane)*4);
      mma16h(accH[g & 1], a, b.x, b.y);
      mma16h(accL[g & 1], a, b.z, b.w);
    }

    // epilogue: s = accH + accL/4096
    float s0 = (accH[0][0]+accH[1][0]) + (accL[0][0]+accL[1][0])*LO_INV;
    float s1 = (accH[0][1]+accH[1][1]) + (accL[0][1]+accL[1][1])*LO_INV;
    float s2 = (accH[0][2]+accH[1][2]) + (accL[0][2]+accL[1][2])*LO_INV;
    float s3 = (accH[0][3]+accH[1][3]) + (accL[0][3]+accL[1][3])*LO_INV;
    float o00 = tanhf(s0 + pv0 + u_b0);
    float o01 = tanhf(s1 + pv1 + u_b1);
    float o10 = tanhf(s2 + pv2 + u_b0);
    float o11 = tanhf(s3 + pv3 + u_b1);

    if (t < SS-1){
      const int nb = (t & 1) ^ 1;
      *(uint2*)(&g_ha[nb][by][gA][wm][lslot]) = make_uint2(hpack(o00, o01), hpack(o10, o11));
      __syncthreads();   // all CTA reads of A done + fragment STGs issued before release
      if (tid == 0)
        asm volatile("red.release.gpu.global.add.u32 [%0], %1;"
                     :: "l"(&g_wc[by][c_w][0]), "r"(1u) : "memory");
    } else {
      g_h[(size_t)mr*HH + nc]       = o00;
      g_h[(size_t)mr*HH + nc + 1]   = o01;
      g_h[(size_t)(mr+8)*HH + nc]   = o10;
      g_h[(size_t)(mr+8)*HH + nc+1] = o11;
    }
  }
}

__global__ void k_final(const float* __restrict__ Vw, const float* __restrict__ Vb, float* __restrict__ out){
  int b = blockIdx.x;
  const float* h = g_h + (size_t)b*HH;
  float s = 0.f;
  for (int k = threadIdx.x; k < HH; k += 128) s += h[k]*Vw[k];
  #pragma unroll
  for (int o=16;o;o>>=1) s += __shfl_down_sync(0xffffffffu, s, o);
  __shared__ float red[4];
  if ((threadIdx.x & 31) == 0) red[threadIdx.x>>5] = s;
  __syncthreads();
  if (threadIdx.x == 0){
    float tot = red[0]+red[1]+red[2]+red[3] + Vb[0];
    out[b] = 1.f/(1.f + expf(-tot));
  }
}

extern "C" void kernel_launch(void* const* d_in, const int* in_sizes, int n_in,
                              void* d_out, int out_size){
  (void)in_sizes; (void)n_in; (void)out_size;
  const int*   x   = (const int*)d_in[0];
  const float* emb = (const float*)d_in[1];
  const float* Ww  = (const float*)d_in[2];
  const float* Wb  = (const float*)d_in[3];
  const float* Uw  = (const float*)d_in[4];
  const float* Ubv = (const float*)d_in[5];
  const float* Vw  = (const float*)d_in[6];
  const float* Vb  = (const float*)d_in[7];
  float* out = (float*)d_out;

  static bool attr_done = false;
  if (!attr_done){
    cudaFuncSetAttribute(k_scan, cudaFuncAttributeMaxDynamicSharedMemorySize, SMEM_BYTES);
    attr_done = true;
  }

  k_init<<<256, 256>>>();
  k_pre<<<dim3(HH/64, TOK/64), 256>>>(x, emb, Ww, Wb);
  k_scan<<<dim3(32, 4), 256, SMEM_BYTES>>>(Uw, Ubv);
  k_final<<<BB, 128>>>(Vw, Vb, out);
}

// round 14
// speedup vs baseline: 3.5528x; 1.3523x over previous
#include <cuda_runtime.h>
#include <cuda_fp16.h>
#include <cstdint>

#define BB 128
#define SS 512
#define EE 512
#define HH 1024
#define TOK (BB*SS)

// Scratch (allocation-free rule: __device__ globals)
__device__ float g_pre[(size_t)TOK * HH];        // [s*B + b][h], fp32
__device__ float g_h[BB * HH];                   // final hidden state
// packed A fragments (fp16 h): [buf][mgroup][g(64 k16-groups)][wm][lane*4+word] fp16x2 words
__device__ __align__(16) unsigned g_ha[2][4][64][2][128];
// per-(mgroup, chunk) monotonic write counters, padded to 128B lines
__device__ unsigned g_wc[4][8][32];

__device__ __forceinline__ void mma16h(float c[4], uint4 a, unsigned b0, unsigned b1){
  asm volatile("mma.sync.aligned.m16n8k16.row.col.f32.f16.f16.f32 "
    "{%0,%1,%2,%3}, {%4,%5,%6,%7}, {%8,%9}, {%0,%1,%2,%3};"
    : "+f"(c[0]),"+f"(c[1]),"+f"(c[2]),"+f"(c[3])
    : "r"(a.x),"r"(a.y),"r"(a.z),"r"(a.w),"r"(b0),"r"(b1));
}
__device__ __forceinline__ void mma16hh(unsigned c[2], uint4 a, unsigned b0, unsigned b1){
  asm volatile("mma.sync.aligned.m16n8k16.row.col.f16.f16.f16.f16 "
    "{%0,%1}, {%2,%3,%4,%5}, {%6,%7}, {%0,%1};"
    : "+r"(c[0]),"+r"(c[1])
    : "r"(a.x),"r"(a.y),"r"(a.z),"r"(a.w),"r"(b0),"r"(b1));
}
__device__ __forceinline__ unsigned hpack(float x, float y){
  return (unsigned)__half_as_ushort(__float2half_rn(x))
       | ((unsigned)__half_as_ushort(__float2half_rn(y)) << 16);
}
__device__ __forceinline__ void waitflag(const unsigned* p, unsigned tgt){
  unsigned v;
  do { asm volatile("ld.global.acquire.gpu.u32 %0, [%1];" : "=r"(v) : "l"(p) : "memory"); } while (v < tgt);
}
__device__ __forceinline__ uint4 ldgcg4(const unsigned* p){
  uint4 v;
  asm volatile("ld.global.cg.v4.u32 {%0,%1,%2,%3}, [%4];"
    : "=r"(v.x),"=r"(v.y),"=r"(v.z),"=r"(v.w) : "l"(p));
  return v;
}

__global__ void k_init(){
  int i = blockIdx.x*blockDim.x + threadIdx.x;
  // zero packed-A buffer 0 (h0 = 0): 4*64*2*128 = 65536 words = 16384 uint4
  if (i < 16384) ((uint4*)g_ha)[i] = make_uint4(0,0,0,0);
  if (i < 4*8*32) ((unsigned*)g_wc)[i] = 0u;
}

// pre[s*B+b][h] = dot(emb[x[b][s]], W[h]) + Wb[h]   (M=65536, N=1024, K=512)
// fp16 m16n8k16 single-term (11 mantissa bits == the tf32 it replaces).
// Tiles: BM=64, BN=64, BK=32, 256 threads, warps 4(m) x 2(n), warp tile 16x32.
__global__ __launch_bounds__(256) void k_pre(const int* __restrict__ x, const float* __restrict__ emb,
                                             const float* __restrict__ Ww, const float* __restrict__ Wb){
  __shared__ unsigned Ash[64][17];   // [row][k-pair], word = (v[2p], v[2p+1]) fp16x2
  __shared__ unsigned Bsh[64][17];
  __shared__ const float* rowp[64];
  const int tid = threadIdx.x;
  const int m0 = blockIdx.y*64, n0 = blockIdx.x*64;
  if (tid < 64){
    int tok = m0 + tid;
    int b = tok & (BB-1), s = tok >> 7;
    rowp[tid] = emb + (size_t)x[b*SS + s]*EE;
  }
  __syncthreads();
  const int lane = tid & 31, wid = tid >> 5;
  const int wm = wid >> 1, wn = wid & 1;
  const int gr = lane >> 2, gq = lane & 3;
  const int lr = tid >> 2, lc = (tid & 3);     // load row, col-block (8 floats)
  float acc[4][4];
  #pragma unroll
  for (int i=0;i<4;i++){ acc[i][0]=0.f; acc[i][1]=0.f; acc[i][2]=0.f; acc[i][3]=0.f; }

  for (int kt = 0; kt < EE/32; ++kt){
    const int k0 = kt*32 + lc*8;
    {
      float4 v0 = *(const float4*)(rowp[lr] + k0);
      float4 v1 = *(const float4*)(rowp[lr] + k0 + 4);
      Ash[lr][lc*4+0] = hpack(v0.x, v0.y);
      Ash[lr][lc*4+1] = hpack(v0.z, v0.w);
      Ash[lr][lc*4+2] = hpack(v1.x, v1.y);
      Ash[lr][lc*4+3] = hpack(v1.z, v1.w);
      const float* br = Ww + (size_t)(n0+lr)*EE + k0;
      float4 w0 = *(const float4*)(br);
      float4 w1 = *(const float4*)(br + 4);
      Bsh[lr][lc*4+0] = hpack(w0.x, w0.y);
      Bsh[lr][lc*4+1] = hpack(w0.z, w0.w);
      Bsh[lr][lc*4+2] = hpack(w1.x, w1.y);
      Bsh[lr][lc*4+3] = hpack(w1.z, w1.w);
    }
    __syncthreads();
    #pragma unroll
    for (int g = 0; g < 2; ++g){
      uint4 a;
      a.x = Ash[wm*16+gr  ][g*8+gq];
      a.y = Ash[wm*16+gr+8][g*8+gq];
      a.z = Ash[wm*16+gr  ][g*8+gq+4];
      a.w = Ash[wm*16+gr+8][g*8+gq+4];
      #pragma unroll
      for (int nf=0; nf<4; ++nf){
        int nr = wn*32 + nf*8 + gr;
        mma16h(acc[nf], a, Bsh[nr][g*8+gq], Bsh[nr][g*8+gq+4]);
      }
    }
    __syncthreads();
  }
  #pragma unroll
  for (int nf=0; nf<4; ++nf){
    int nc = n0 + wn*32 + nf*8 + 2*gq;
    int mr = m0 + wm*16 + gr;
    float wb0 = Wb[nc], wb1 = Wb[nc+1];
    g_pre[(size_t)mr*HH + nc]        = acc[nf][0] + wb0;
    g_pre[(size_t)mr*HH + nc + 1]    = acc[nf][1] + wb1;
    g_pre[(size_t)(mr+8)*HH + nc]    = acc[nf][2] + wb0;
    g_pre[(size_t)(mr+8)*HH + nc+1]  = acc[nf][3] + wb1;
  }
}

// ---------------- persistent recurrence: fp16, register-direct A, 1 sync/step ----------------
// 128 CTAs = 4 independent mgroups (by) x 32 n-slices (bx). 256 threads, 8 warps.
// A fragments read straight from L2 (ld.global.cg.v4) -- no SMEM staging at all.
// D_H(f32) += a*bh ; D_L(f16 acc) += a*(4096*bl) ; s = D_H + D_L/4096.
// B (U) resident in SMEM, interleaved (bh0,bh1,bl0,bl1) -> one LDS.128 per group.
#define SM_B  0
#define SM_UB 131072
#define SMEM_BYTES 131200
#define LO_SCALE 4096.0f
#define LO_INV   (1.0f/4096.0f)

__global__ __launch_bounds__(256, 1) void k_scan(const float* __restrict__ U, const float* __restrict__ Ub){
  extern __shared__ unsigned smw[];   // word-addressed
  const int tid = threadIdx.x, lane = tid & 31, wid = tid >> 5;
  const int gr = lane >> 2, gq = lane & 3;
  const int wm = wid & 1, wn = wid >> 1;        // 2 m-halves x 4 n-blocks of 8
  const int bx = blockIdx.x, by = blockIdx.y;
  const int n0 = bx*32, m0 = by*32;

  // ---- pack U slice (rows n0..n0+31, full K) into fp16 hi + scaled-lo B-fragments ----
  for (int e = tid; e < 64*4*32; e += 256){
    int ln = e & 31, nf = (e >> 5) & 3, g = e >> 7;
    int rr = ln >> 2, qq = ln & 3;
    const float* ur = U + (size_t)(n0 + nf*8 + rr)*HH + g*16 + 2*qq;
    float v0 = ur[0], v1 = ur[1], v2 = ur[8], v3 = ur[9];
    float h0 = __half2float(__float2half_rn(v0));
    float h1 = __half2float(__float2half_rn(v1));
    float h2 = __half2float(__float2half_rn(v2));
    float h3 = __half2float(__float2half_rn(v3));
    unsigned bh0 = hpack(v0, v1), bh1 = hpack(v2, v3);
    unsigned bl0 = hpack((v0-h0)*LO_SCALE, (v1-h1)*LO_SCALE);
    unsigned bl1 = hpack((v2-h2)*LO_SCALE, (v3-h3)*LO_SCALE);
    unsigned off = (unsigned)(((g*4 + nf)*32 + ln)*4);
    *(uint4*)(smw + SM_B/4 + off) = make_uint4(bh0, bh1, bl0, bl1);
  }
  if (tid < 32) ((float*)(smw + SM_UB/4))[tid] = Ub[n0 + tid];

  // epilogue / producer constants
  const int nc = n0 + wn*8 + 2*gq;              // output columns nc, nc+1
  const int mr = m0 + wm*16 + gr;               // output rows mr, mr+8
  const float u_b0 = Ub[nc], u_b1 = Ub[nc+1];
  const int gA = bx*2 + (wn >> 1);              // destination k16-group of columns nc
  const int wbase = (wn & 1)*2;
  const int lslot = (gr*4 + gq)*4 + wbase;
  const int c_w = bx >> 2;                      // this CTA's write chunk
  __syncthreads();

  for (int t = 0; t < SS; ++t){
    const unsigned* ga = &g_ha[t & 1][by][0][0][0];   // 16384 words, fragment-packed
    const float* __restrict__ pre = g_pre + (size_t)t*BB*HH;
    const unsigned tgt = 4u*(unsigned)t;

    const float pv0 = pre[(size_t)mr*HH + nc];
    const float pv1 = pre[(size_t)mr*HH + nc + 1];
    const float pv2 = pre[(size_t)(mr+8)*HH + nc];
    const float pv3 = pre[(size_t)(mr+8)*HH + nc + 1];

    // gate: 8 lanes poll the 8 chunk flags in parallel
    if (lane < 8) waitflag(&g_wc[by][lane][0], tgt);
    __syncwarp();

    float accH[2][4];
    unsigned accL[2][2];
    #pragma unroll
    for (int i=0;i<2;++i){
      accH[i][0]=0.f;accH[i][1]=0.f;accH[i][2]=0.f;accH[i][3]=0.f;
      accL[i][0]=0u; accL[i][1]=0u;
    }

    // 64 uninterrupted k16 groups; A straight from L2
    const unsigned* bp = smw + SM_B/4;
    #pragma unroll 16
    for (int g = 0; g < 64; ++g){
      uint4 a = ldgcg4(ga + ((g*2 + wm)*32 + lane)*4);
      uint4 b = *(const uint4*)(bp + ((g*4 + wn)*32 + lane)*4);
      mma16h(accH[g & 1], a, b.x, b.y);
      mma16hh(accL[g & 1], a, b.z, b.w);
    }

    // epilogue: s = accH + accL/4096
    __half2 lA0 = *(__half2*)&accL[0][0];
    __half2 lA1 = *(__half2*)&accL[0][1];
    __half2 lB0 = *(__half2*)&accL[1][0];
    __half2 lB1 = *(__half2*)&accL[1][1];
    float s0 = (accH[0][0]+accH[1][0]) + (__low2float(lA0)+__low2float(lB0))*LO_INV;
    float s1 = (accH[0][1]+accH[1][1]) + (__high2float(lA0)+__high2float(lB0))*LO_INV;
    float s2 = (accH[0][2]+accH[1][2]) + (__low2float(lA1)+__low2float(lB1))*LO_INV;
    float s3 = (accH[0][3]+accH[1][3]) + (__high2float(lA1)+__high2float(lB1))*LO_INV;
    float o00 = tanhf(s0 + pv0 + u_b0);
    float o01 = tanhf(s1 + pv1 + u_b1);
    float o10 = tanhf(s2 + pv2 + u_b0);
    float o11 = tanhf(s3 + pv3 + u_b1);

    if (t < SS-1){
      const int nb = (t & 1) ^ 1;
      *(uint2*)(&g_ha[nb][by][gA][wm][lslot]) = make_uint2(hpack(o00, o01), hpack(o10, o11));
      __syncthreads();   // all CTA A-reads consumed + fragment STGs issued before release
      if (tid == 0)
        asm volatile("red.release.gpu.global.add.u32 [%0], %1;"
                     :: "l"(&g_wc[by][c_w][0]), "r"(1u) : "memory");
    } else {
      g_h[(size_t)mr*HH + nc]       = o00;
      g_h[(size_t)mr*HH + nc + 1]   = o01;
      g_h[(size_t)(mr+8)*HH + nc]   = o10;
      g_h[(size_t)(mr+8)*HH + nc+1] = o11;
    }
  }
}

__global__ void k_final(const float* __restrict__ Vw, const float* __restrict__ Vb, float* __restrict__ out){
  int b = blockIdx.x;
  const float* h = g_h + (size_t)b*HH;
  float s = 0.f;
  for (int k = threadIdx.x; k < HH; k += 128) s += h[k]*Vw[k];
  #pragma unroll
  for (int o=16;o;o>>=1) s += __shfl_down_sync(0xffffffffu, s, o);
  __shared__ float red[4];
  if ((threadIdx.x & 31) == 0) red[threadIdx.x>>5] = s;
  __syncthreads();
  if (threadIdx.x == 0){
    float tot = red[0]+red[1]+red[2]+red[3] + Vb[0];
    out[b] = 1.f/(1.f + expf(-tot));
  }
}

extern "C" void kernel_launch(void* const* d_in, const int* in_sizes, int n_in,
                              void* d_out, int out_size){
  (void)in_sizes; (void)n_in; (void)out_size;
  const int*   x   = (const int*)d_in[0];
  const float* emb = (const float*)d_in[1];
  const float* Ww  = (const float*)d_in[2];
  const float* Wb  = (const float*)d_in[3];
  const float* Uw  = (const float*)d_in[4];
  const float* Ubv = (const float*)d_in[5];
  const float* Vw  = (const float*)d_in[6];
  const float* Vb  = (const float*)d_in[7];
  float* out = (float*)d_out;

  static bool attr_done = false;
  if (!attr_done){
    cudaFuncSetAttribute(k_scan, cudaFuncAttributeMaxDynamicSharedMemorySize, SMEM_BYTES);
    attr_done = true;
  }

  k_init<<<256, 256>>>();
  k_pre<<<dim3(HH/64, TOK/64), 256>>>(x, emb, Ww, Wb);
  k_scan<<<dim3(32, 4), 256, SMEM_BYTES>>>(Uw, Ubv);
  k_final<<<BB, 128>>>(Vw, Vb, out);
}

// round 15
// speedup vs baseline: 4.3400x; 1.2216x over previous
#include <cuda_runtime.h>
#include <cuda_fp16.h>
#include <cstdint>

#define BB 128
#define SS 512
#define EE 512
#define HH 1024
#define TOK (BB*SS)

// Scratch (allocation-free rule: __device__ globals)
__device__ float g_pre[(size_t)TOK * HH];        // [s*B + b][h], fp32
__device__ float g_h[BB * HH];                   // final hidden state
// packed A fragments (fp16 h): [buf][mgroup][g(64 k16-groups)][wm][lane*4+word] fp16x2 words
__device__ __align__(16) unsigned g_ha[2][4][64][2][128];
// per-(mgroup, chunk) monotonic write counters, padded to 128B lines
__device__ unsigned g_wc[4][8][32];

__device__ __forceinline__ void mma16h(float c[4], uint4 a, unsigned b0, unsigned b1){
  asm volatile("mma.sync.aligned.m16n8k16.row.col.f32.f16.f16.f32 "
    "{%0,%1,%2,%3}, {%4,%5,%6,%7}, {%8,%9}, {%0,%1,%2,%3};"
    : "+f"(c[0]),"+f"(c[1]),"+f"(c[2]),"+f"(c[3])
    : "r"(a.x),"r"(a.y),"r"(a.z),"r"(a.w),"r"(b0),"r"(b1));
}
__device__ __forceinline__ void mma16hh(unsigned c[2], uint4 a, unsigned b0, unsigned b1){
  asm volatile("mma.sync.aligned.m16n8k16.row.col.f16.f16.f16.f16 "
    "{%0,%1}, {%2,%3,%4,%5}, {%6,%7}, {%0,%1};"
    : "+r"(c[0]),"+r"(c[1])
    : "r"(a.x),"r"(a.y),"r"(a.z),"r"(a.w),"r"(b0),"r"(b1));
}
__device__ __forceinline__ unsigned hpack(float x, float y){
  return (unsigned)__half_as_ushort(__float2half_rn(x))
       | ((unsigned)__half_as_ushort(__float2half_rn(y)) << 16);
}
__device__ __forceinline__ void waitflag(const unsigned* p, unsigned tgt){
  unsigned v;
  do { asm volatile("ld.global.acquire.gpu.u32 %0, [%1];" : "=r"(v) : "l"(p) : "memory"); } while (v < tgt);
}
__device__ __forceinline__ uint4 ldgcg4(const unsigned* p){
  uint4 v;
  asm volatile("ld.global.cg.v4.u32 {%0,%1,%2,%3}, [%4];"
    : "=r"(v.x),"=r"(v.y),"=r"(v.z),"=r"(v.w) : "l"(p));
  return v;
}

__global__ void k_init(){
  int i = blockIdx.x*blockDim.x + threadIdx.x;
  // zero packed-A buffer 0 (h0 = 0): 4*64*2*128 = 65536 words = 16384 uint4
  if (i < 16384) ((uint4*)g_ha)[i] = make_uint4(0,0,0,0);
  if (i < 4*8*32) ((unsigned*)g_wc)[i] = 0u;
}

// pre[s*B+b][h] = dot(emb[x[b][s]], W[h]) + Wb[h]   (M=65536, N=1024, K=512)
// fp16 m16n8k16 single-term. BM=64, BN=64, BK=32, 256 threads. (R14-proven)
__global__ __launch_bounds__(256) void k_pre(const int* __restrict__ x, const float* __restrict__ emb,
                                             const float* __restrict__ Ww, const float* __restrict__ Wb){
  __shared__ unsigned Ash[64][17];   // [row][k-pair], word = (v[2p], v[2p+1]) fp16x2
  __shared__ unsigned Bsh[64][17];
  __shared__ const float* rowp[64];
  const int tid = threadIdx.x;
  const int m0 = blockIdx.y*64, n0 = blockIdx.x*64;
  if (tid < 64){
    int tok = m0 + tid;
    int b = tok & (BB-1), s = tok >> 7;
    rowp[tid] = emb + (size_t)x[b*SS + s]*EE;
  }
  __syncthreads();
  const int lane = tid & 31, wid = tid >> 5;
  const int wm = wid >> 1, wn = wid & 1;
  const int gr = lane >> 2, gq = lane & 3;
  const int lr = tid >> 2, lc = (tid & 3);
  float acc[4][4];
  #pragma unroll
  for (int i=0;i<4;i++){ acc[i][0]=0.f; acc[i][1]=0.f; acc[i][2]=0.f; acc[i][3]=0.f; }

  for (int kt = 0; kt < EE/32; ++kt){
    const int k0 = kt*32 + lc*8;
    {
      float4 v0 = *(const float4*)(rowp[lr] + k0);
      float4 v1 = *(const float4*)(rowp[lr] + k0 + 4);
      Ash[lr][lc*4+0] = hpack(v0.x, v0.y);
      Ash[lr][lc*4+1] = hpack(v0.z, v0.w);
      Ash[lr][lc*4+2] = hpack(v1.x, v1.y);
      Ash[lr][lc*4+3] = hpack(v1.z, v1.w);
      const float* br = Ww + (size_t)(n0+lr)*EE + k0;
      float4 w0 = *(const float4*)(br);
      float4 w1 = *(const float4*)(br + 4);
      Bsh[lr][lc*4+0] = hpack(w0.x, w0.y);
      Bsh[lr][lc*4+1] = hpack(w0.z, w0.w);
      Bsh[lr][lc*4+2] = hpack(w1.x, w1.y);
      Bsh[lr][lc*4+3] = hpack(w1.z, w1.w);
    }
    __syncthreads();
    #pragma unroll
    for (int g = 0; g < 2; ++g){
      uint4 a;
      a.x = Ash[wm*16+gr  ][g*8+gq];
      a.y = Ash[wm*16+gr+8][g*8+gq];
      a.z = Ash[wm*16+gr  ][g*8+gq+4];
      a.w = Ash[wm*16+gr+8][g*8+gq+4];
      #pragma unroll
      for (int nf=0; nf<4; ++nf){
        int nr = wn*32 + nf*8 + gr;
        mma16h(acc[nf], a, Bsh[nr][g*8+gq], Bsh[nr][g*8+gq+4]);
      }
    }
    __syncthreads();
  }
  #pragma unroll
  for (int nf=0; nf<4; ++nf){
    int nc = n0 + wn*32 + nf*8 + 2*gq;
    int mr = m0 + wm*16 + gr;
    float wb0 = Wb[nc], wb1 = Wb[nc+1];
    g_pre[(size_t)mr*HH + nc]        = acc[nf][0] + wb0;
    g_pre[(size_t)mr*HH + nc + 1]    = acc[nf][1] + wb1;
    g_pre[(size_t)(mr+8)*HH + nc]    = acc[nf][2] + wb0;
    g_pre[(size_t)(mr+8)*HH + nc+1]  = acc[nf][3] + wb1;
  }
}

// ---------------- persistent recurrence: fp16, m x k warp tiling ----------------
// 128 CTAs = 4 mgroups (by) x 32 n-slices (bx). 256 threads, 8 warps.
// Warps: wm = wid&1 (m-half), wks = wid>>1 (k-quarter). Warp tile m16 x n32 x k256:
// each A fragment LDG'd from L2 exactly ONCE per CTA (8MB/step chip-wide, was 32MB).
// D_H(f32) += a*bh ; D_L(f16 acc) += a*(4096*bl) ; s = D_H + D_L/4096.
// Epilogue: k-quarter partials reduced via SMEM ([nf][q][wm][lane] float4, conflict-free).
#define SM_B   0
#define SM_UB  131072
#define SM_RED 131200
#define SMEM_BYTES 147584
#define LO_SCALE 4096.0f
#define LO_INV   (1.0f/4096.0f)

__global__ __launch_bounds__(256, 1) void k_scan(const float* __restrict__ U, const float* __restrict__ Ub){
  extern __shared__ unsigned smw[];   // word-addressed
  const int tid = threadIdx.x, lane = tid & 31, wid = tid >> 5;
  const int gr = lane >> 2, gq = lane & 3;
  const int wm = wid & 1, wks = wid >> 1;       // 2 m-halves x 4 k-quarters
  const int bx = blockIdx.x, by = blockIdx.y;
  const int n0 = bx*32, m0 = by*32;

  // ---- pack U slice (rows n0..n0+31, full K) into fp16 hi + scaled-lo B-fragments ----
  for (int e = tid; e < 64*4*32; e += 256){
    int ln = e & 31, nf = (e >> 5) & 3, g = e >> 7;
    int rr = ln >> 2, qq = ln & 3;
    const float* ur = U + (size_t)(n0 + nf*8 + rr)*HH + g*16 + 2*qq;
    float v0 = ur[0], v1 = ur[1], v2 = ur[8], v3 = ur[9];
    float h0 = __half2float(__float2half_rn(v0));
    float h1 = __half2float(__float2half_rn(v1));
    float h2 = __half2float(__float2half_rn(v2));
    float h3 = __half2float(__float2half_rn(v3));
    unsigned bh0 = hpack(v0, v1), bh1 = hpack(v2, v3);
    unsigned bl0 = hpack((v0-h0)*LO_SCALE, (v1-h1)*LO_SCALE);
    unsigned bl1 = hpack((v2-h2)*LO_SCALE, (v3-h3)*LO_SCALE);
    unsigned off = (unsigned)(((g*4 + nf)*32 + ln)*4);
    *(uint4*)(smw + SM_B/4 + off) = make_uint4(bh0, bh1, bl0, bl1);
  }
  if (tid < 32) ((float*)(smw + SM_UB/4))[tid] = Ub[n0 + tid];

  // epilogue / producer constants (R12-proven mapping with wn := wks)
  const int nc = n0 + wks*8 + 2*gq;             // output columns nc, nc+1
  const int mr = m0 + wm*16 + gr;               // output rows mr, mr+8
  const float u_b0 = Ub[nc], u_b1 = Ub[nc+1];
  const int gA = bx*2 + (wks >> 1);             // destination k16-group of columns nc
  const int wbase = (wks & 1)*2;
  const int lslot = (gr*4 + gq)*4 + wbase;
  const int c_w = bx >> 2;                      // this CTA's write chunk
  float* red = (float*)(smw + SM_RED/4);        // [nf][q][wm][lane][4]
  __syncthreads();

  for (int t = 0; t < SS; ++t){
    const unsigned* ga = &g_ha[t & 1][by][0][0][0];   // 16384 words, fragment-packed
    const float* __restrict__ pre = g_pre + (size_t)t*BB*HH;
    const unsigned tgt = 4u*(unsigned)t;

    const float pv0 = pre[(size_t)mr*HH + nc];
    const float pv1 = pre[(size_t)mr*HH + nc + 1];
    const float pv2 = pre[(size_t)(mr+8)*HH + nc];
    const float pv3 = pre[(size_t)(mr+8)*HH + nc + 1];

    // gate: this warp only needs chunks wks*2, wks*2+1 (its 16 k-groups)
    if (lane < 2) waitflag(&g_wc[by][wks*2 + lane][0], tgt);
    __syncwarp();

    float accH[4][4];
    unsigned accL[4][2];
    #pragma unroll
    for (int i=0;i<4;++i){
      accH[i][0]=0.f;accH[i][1]=0.f;accH[i][2]=0.f;accH[i][3]=0.f;
      accL[i][0]=0u; accL[i][1]=0u;
    }

    // 16 k16 groups x 4 n-fragments; A read once per CTA
    const unsigned* bp = smw + SM_B/4;
    #pragma unroll
    for (int gl = 0; gl < 16; ++gl){
      const int g = wks*16 + gl;
      uint4 a = ldgcg4(ga + ((g*2 + wm)*32 + lane)*4);
      #pragma unroll
      for (int nf = 0; nf < 4; ++nf){
        uint4 b = *(const uint4*)(bp + ((g*4 + nf)*32 + lane)*4);
        mma16h(accH[nf], a, b.x, b.y);
        mma16hh(accL[nf], a, b.z, b.w);
      }
    }

    // ---- k-quarter reduction via SMEM ----
    #pragma unroll
    for (int nf = 0; nf < 4; ++nf){
      __half2 l0 = *(__half2*)&accL[nf][0];
      __half2 l1 = *(__half2*)&accL[nf][1];
      float4 v;
      v.x = accH[nf][0] + __low2float(l0)*LO_INV;
      v.y = accH[nf][1] + __high2float(l0)*LO_INV;
      v.z = accH[nf][2] + __low2float(l1)*LO_INV;
      v.w = accH[nf][3] + __high2float(l1)*LO_INV;
      *(float4*)(red + (((nf*4 + wks)*2 + wm)*32 + lane)*4) = v;
    }
    __syncthreads();
    float4 p0 = *(const float4*)(red + (((wks*4 + 0)*2 + wm)*32 + lane)*4);
    float4 p1 = *(const float4*)(red + (((wks*4 + 1)*2 + wm)*32 + lane)*4);
    float4 p2 = *(const float4*)(red + (((wks*4 + 2)*2 + wm)*32 + lane)*4);
    float4 p3 = *(const float4*)(red + (((wks*4 + 3)*2 + wm)*32 + lane)*4);
    float s0 = (p0.x + p1.x) + (p2.x + p3.x);
    float s1 = (p0.y + p1.y) + (p2.y + p3.y);
    float s2 = (p0.z + p1.z) + (p2.z + p3.z);
    float s3 = (p0.w + p1.w) + (p2.w + p3.w);

    float o00 = tanhf(s0 + pv0 + u_b0);
    float o01 = tanhf(s1 + pv1 + u_b1);
    float o10 = tanhf(s2 + pv2 + u_b0);
    float o11 = tanhf(s3 + pv3 + u_b1);

    if (t < SS-1){
      const int nb = (t & 1) ^ 1;
      *(uint2*)(&g_ha[nb][by][gA][wm][lslot]) = make_uint2(hpack(o00, o01), hpack(o10, o11));
      __syncthreads();   // A reads + red reads done; fragment STGs issued before release
      if (tid == 0)
        asm volatile("red.release.gpu.global.add.u32 [%0], %1;"
                     :: "l"(&g_wc[by][c_w][0]), "r"(1u) : "memory");
    } else {
      g_h[(size_t)mr*HH + nc]       = o00;
      g_h[(size_t)mr*HH + nc + 1]   = o01;
      g_h[(size_t)(mr+8)*HH + nc]   = o10;
      g_h[(size_t)(mr+8)*HH + nc+1] = o11;
    }
  }
}

__global__ void k_final(const float* __restrict__ Vw, const float* __restrict__ Vb, float* __restrict__ out){
  int b = blockIdx.x;
  const float* h = g_h + (size_t)b*HH;
  float s = 0.f;
  for (int k = threadIdx.x; k < HH; k += 128) s += h[k]*Vw[k];
  #pragma unroll
  for (int o=16;o;o>>=1) s += __shfl_down_sync(0xffffffffu, s, o);
  __shared__ float red[4];
  if ((threadIdx.x & 31) == 0) red[threadIdx.x>>5] = s;
  __syncthreads();
  if (threadIdx.x == 0){
    float tot = red[0]+red[1]+red[2]+red[3] + Vb[0];
    out[b] = 1.f/(1.f + expf(-tot));
  }
}

extern "C" void kernel_launch(void* const* d_in, const int* in_sizes, int n_in,
                              void* d_out, int out_size){
  (void)in_sizes; (void)n_in; (void)out_size;
  const int*   x   = (const int*)d_in[0];
  const float* emb = (const float*)d_in[1];
  const float* Ww  = (const float*)d_in[2];
  const float* Wb  = (const float*)d_in[3];
  const float* Uw  = (const float*)d_in[4];
  const float* Ubv = (const float*)d_in[5];
  const float* Vw  = (const float*)d_in[6];
  const float* Vb  = (const float*)d_in[7];
  float* out = (float*)d_out;

  static bool attr_done = false;
  if (!attr_done){
    cudaFuncSetAttribute(k_scan, cudaFuncAttributeMaxDynamicSharedMemorySize, SMEM_BYTES);
    attr_done = true;
  }

  k_init<<<256, 256>>>();
  k_pre<<<dim3(HH/64, TOK/64), 256>>>(x, emb, Ww, Wb);
  k_scan<<<dim3(32, 4), 256, SMEM_BYTES>>>(Uw, Ubv);
  k_final<<<BB, 128>>>(Vw, Vb, out);
}

// round 16
// speedup vs baseline: 4.4504x; 1.0254x over previous
#include <cuda_runtime.h>
#include <cuda_fp16.h>
#include <cstdint>

#define BB 128
#define SS 512
#define EE 512
#define HH 1024
#define VOCAB 32000
#define TOK (BB*SS)

// Scratch (allocation-free rule: __device__ globals)
__device__ float g_pre[(size_t)TOK * HH];        // [s*B + b][h], fp32
__device__ float g_h[BB * HH];                   // final hidden state
__device__ unsigned short g_emb16[(size_t)VOCAB * EE];  // fp16 embedding table
__device__ unsigned short g_w16[(size_t)HH * EE];       // fp16 W weights
// packed A fragments (fp16 h): [buf][mgroup][g(64 k16-groups)][wm][lane*4+word] fp16x2 words
__device__ __align__(16) unsigned g_ha[2][4][64][2][128];
// per-(mgroup, chunk) monotonic write counters, padded to 128B lines
__device__ unsigned g_wc[4][8][32];

__device__ __forceinline__ void mma16h(float c[4], uint4 a, unsigned b0, unsigned b1){
  asm volatile("mma.sync.aligned.m16n8k16.row.col.f32.f16.f16.f32 "
    "{%0,%1,%2,%3}, {%4,%5,%6,%7}, {%8,%9}, {%0,%1,%2,%3};"
    : "+f"(c[0]),"+f"(c[1]),"+f"(c[2]),"+f"(c[3])
    : "r"(a.x),"r"(a.y),"r"(a.z),"r"(a.w),"r"(b0),"r"(b1));
}
__device__ __forceinline__ void mma16hh(unsigned c[2], uint4 a, unsigned b0, unsigned b1){
  asm volatile("mma.sync.aligned.m16n8k16.row.col.f16.f16.f16.f16 "
    "{%0,%1}, {%2,%3,%4,%5}, {%6,%7}, {%0,%1};"
    : "+r"(c[0]),"+r"(c[1])
    : "r"(a.x),"r"(a.y),"r"(a.z),"r"(a.w),"r"(b0),"r"(b1));
}
__device__ __forceinline__ unsigned hpack(float x, float y){
  return (unsigned)__half_as_ushort(__float2half_rn(x))
       | ((unsigned)__half_as_ushort(__float2half_rn(y)) << 16);
}
__device__ __forceinline__ void waitflag(const unsigned* p, unsigned tgt){
  unsigned v;
  do { asm volatile("ld.global.acquire.gpu.u32 %0, [%1];" : "=r"(v) : "l"(p) : "memory"); } while (v < tgt);
}
__device__ __forceinline__ uint4 ldgcg4(const unsigned* p){
  uint4 v;
  asm volatile("ld.global.cg.v4.u32 {%0,%1,%2,%3}, [%4];"
    : "=r"(v.x),"=r"(v.y),"=r"(v.z),"=r"(v.w) : "l"(p));
  return v;
}

__global__ void k_init(){
  int i = blockIdx.x*blockDim.x + threadIdx.x;
  if (i < 16384) ((uint4*)g_ha)[i] = make_uint4(0,0,0,0);
  if (i < 4*8*32) ((unsigned*)g_wc)[i] = 0u;
}

// one-time fp32 -> fp16 conversion of emb and W (vectorized, grid-stride)
__global__ void k_cvt(const float* __restrict__ emb, const float* __restrict__ Ww){
  const size_t NE = (size_t)VOCAB*EE/4, NW = (size_t)HH*EE/4;
  size_t stride = (size_t)gridDim.x*blockDim.x;
  for (size_t i = blockIdx.x*blockDim.x + threadIdx.x; i < NE; i += stride){
    float4 v = ((const float4*)emb)[i];
    ((uint2*)g_emb16)[i] = make_uint2(hpack(v.x, v.y), hpack(v.z, v.w));
  }
  for (size_t i = blockIdx.x*blockDim.x + threadIdx.x; i < NW; i += stride){
    float4 v = ((const float4*)Ww)[i];
    ((uint2*)g_w16)[i] = make_uint2(hpack(v.x, v.y), hpack(v.z, v.w));
  }
}

// pre[s*B+b][h] = dot(emb[x[b][s]], W[h]) + Wb[h]   (M=65536, N=1024, K=512)
// fp16 m16n8k16 single-term, operands pre-converted -> zero cvt in hot loop.
__global__ __launch_bounds__(256) void k_pre(const int* __restrict__ x, const float* __restrict__ Wb){
  __shared__ unsigned Ash[64][17];   // [row][k-pair] fp16x2 words
  __shared__ unsigned Bsh[64][17];
  __shared__ const unsigned short* rowp[64];
  const int tid = threadIdx.x;
  const int m0 = blockIdx.y*64, n0 = blockIdx.x*64;
  if (tid < 64){
    int tok = m0 + tid;
    int b = tok & (BB-1), s = tok >> 7;
    rowp[tid] = g_emb16 + (size_t)x[b*SS + s]*EE;
  }
  __syncthreads();
  const int lane = tid & 31, wid = tid >> 5;
  const int wm = wid >> 1, wn = wid & 1;
  const int gr = lane >> 2, gq = lane & 3;
  const int lr = tid >> 2, lc = (tid & 3);     // load row, 8-half block
  float acc[4][4];
  #pragma unroll
  for (int i=0;i<4;i++){ acc[i][0]=0.f; acc[i][1]=0.f; acc[i][2]=0.f; acc[i][3]=0.f; }

  for (int kt = 0; kt < EE/32; ++kt){
    const int kh = kt*32 + lc*8;    // half offset
    {
      uint4 av = *(const uint4*)(rowp[lr] + kh);
      Ash[lr][lc*4+0] = av.x; Ash[lr][lc*4+1] = av.y;
      Ash[lr][lc*4+2] = av.z; Ash[lr][lc*4+3] = av.w;
      uint4 bv = *(const uint4*)(g_w16 + (size_t)(n0+lr)*EE + kh);
      Bsh[lr][lc*4+0] = bv.x; Bsh[lr][lc*4+1] = bv.y;
      Bsh[lr][lc*4+2] = bv.z; Bsh[lr][lc*4+3] = bv.w;
    }
    __syncthreads();
    #pragma unroll
    for (int g = 0; g < 2; ++g){
      uint4 a;
      a.x = Ash[wm*16+gr  ][g*8+gq];
      a.y = Ash[wm*16+gr+8][g*8+gq];
      a.z = Ash[wm*16+gr  ][g*8+gq+4];
      a.w = Ash[wm*16+gr+8][g*8+gq+4];
      #pragma unroll
      for (int nf=0; nf<4; ++nf){
        int nr = wn*32 + nf*8 + gr;
        mma16h(acc[nf], a, Bsh[nr][g*8+gq], Bsh[nr][g*8+gq+4]);
      }
    }
    __syncthreads();
  }
  #pragma unroll
  for (int nf=0; nf<4; ++nf){
    int nc = n0 + wn*32 + nf*8 + 2*gq;
    int mr = m0 + wm*16 + gr;
    float wb0 = Wb[nc], wb1 = Wb[nc+1];
    g_pre[(size_t)mr*HH + nc]        = acc[nf][0] + wb0;
    g_pre[(size_t)mr*HH + nc + 1]    = acc[nf][1] + wb1;
    g_pre[(size_t)(mr+8)*HH + nc]    = acc[nf][2] + wb0;
    g_pre[(size_t)(mr+8)*HH + nc+1]  = acc[nf][3] + wb1;
  }
}

// ---------------- persistent recurrence: fp16, N=16/CTA, 2 CTAs/SM ----------------
// 256 CTAs = 4 mgroups (by) x 64 n-slices (bx), 2 resident CTAs/SM -> one chain's
// flag-wait hides under the other chain's compute. 256 threads, 8 warps:
// wm = wid&1 (m-half), wks = wid>>1 (k-quarter). Warp tile m16 x n16 x k256.
// D_H(f32) += a*bh ; D_L(f16) += a*(4096*bl) ; s = D_H + D_L/4096.
// Flags: 8 writer CTAs per (by, chunk); tgt = 8t.
#define SM_B   0
#define SM_UB  65536
#define SM_RED 65600
#define SMEM_BYTES 73792
#define LO_SCALE 4096.0f
#define LO_INV   (1.0f/4096.0f)

__global__ __launch_bounds__(256, 2) void k_scan(const float* __restrict__ U, const float* __restrict__ Ub){
  extern __shared__ unsigned smw[];   // word-addressed
  const int tid = threadIdx.x, lane = tid & 31, wid = tid >> 5;
  const int gr = lane >> 2, gq = lane & 3;
  const int wm = wid & 1, wks = wid >> 1;       // 2 m-halves x 4 k-quarters
  const int bx = blockIdx.x, by = blockIdx.y;
  const int n0 = bx*16, m0 = by*32;

  // ---- pack U slice (rows n0..n0+15, full K) into fp16 hi + scaled-lo B-fragments ----
  for (int e = tid; e < 64*2*32; e += 256){
    int ln = e & 31, nf = (e >> 5) & 1, g = e >> 6;
    int rr = ln >> 2, qq = ln & 3;
    const float* ur = U + (size_t)(n0 + nf*8 + rr)*HH + g*16 + 2*qq;
    float v0 = ur[0], v1 = ur[1], v2 = ur[8], v3 = ur[9];
    float h0 = __half2float(__float2half_rn(v0));
    float h1 = __half2float(__float2half_rn(v1));
    float h2 = __half2float(__float2half_rn(v2));
    float h3 = __half2float(__float2half_rn(v3));
    unsigned bh0 = hpack(v0, v1), bh1 = hpack(v2, v3);
    unsigned bl0 = hpack((v0-h0)*LO_SCALE, (v1-h1)*LO_SCALE);
    unsigned bl1 = hpack((v2-h2)*LO_SCALE, (v3-h3)*LO_SCALE);
    unsigned off = (unsigned)(((g*2 + nf)*32 + ln)*4);
    *(uint4*)(smw + SM_B/4 + off) = make_uint4(bh0, bh1, bl0, bl1);
  }
  if (tid < 16) ((float*)(smw + SM_UB/4))[tid] = Ub[n0 + tid];

  // epilogue / producer constants (nfw valid for wks<2; others clamped in-bounds)
  const int nfw = wks & 1;
  const int nc = n0 + nfw*8 + 2*gq;             // output columns nc, nc+1
  const int mr = m0 + wm*16 + gr;               // output rows mr, mr+8
  const float u_b0 = Ub[nc], u_b1 = Ub[nc+1];
  const int gA = bx;                            // 16 cols == exactly one k16-group
  const int lslot = (gr*4 + gq)*4 + nfw*2;
  const int c_w = bx >> 3;                      // this CTA's write chunk (8 writers each)
  float* red = (float*)(smw + SM_RED/4);        // [nf(2)][q(4)][wm(2)][lane(32)] float4
  __syncthreads();

  for (int t = 0; t < SS; ++t){
    const unsigned* ga = &g_ha[t & 1][by][0][0][0];   // 16384 words, fragment-packed
    const float* __restrict__ pre = g_pre + (size_t)t*BB*HH;
    const unsigned tgt = 8u*(unsigned)t;

    const float pv0 = pre[(size_t)mr*HH + nc];
    const float pv1 = pre[(size_t)mr*HH + nc + 1];
    const float pv2 = pre[(size_t)(mr+8)*HH + nc];
    const float pv3 = pre[(size_t)(mr+8)*HH + nc + 1];

    // gate: this warp only needs chunks wks*2, wks*2+1
    if (lane < 2) waitflag(&g_wc[by][wks*2 + lane][0], tgt);
    __syncwarp();

    float accH[2][4];
    unsigned accL[2][2];
    #pragma unroll
    for (int i=0;i<2;++i){
      accH[i][0]=0.f;accH[i][1]=0.f;accH[i][2]=0.f;accH[i][3]=0.f;
      accL[i][0]=0u; accL[i][1]=0u;
    }

    // 16 k16 groups x 2 n-fragments; A read once per CTA
    const unsigned* bp = smw + SM_B/4;
    #pragma unroll
    for (int gl = 0; gl < 16; ++gl){
      const int g = wks*16 + gl;
      uint4 a = ldgcg4(ga + ((g*2 + wm)*32 + lane)*4);
      #pragma unroll
      for (int nf = 0; nf < 2; ++nf){
        uint4 b = *(const uint4*)(bp + ((g*2 + nf)*32 + lane)*4);
        mma16h(accH[nf], a, b.x, b.y);
        mma16hh(accL[nf], a, b.z, b.w);
      }
    }

    // ---- k-quarter reduction via SMEM ----
    #pragma unroll
    for (int nf = 0; nf < 2; ++nf){
      __half2 l0 = *(__half2*)&accL[nf][0];
      __half2 l1 = *(__half2*)&accL[nf][1];
      float4 v;
      v.x = accH[nf][0] + __low2float(l0)*LO_INV;
      v.y = accH[nf][1] + __high2float(l0)*LO_INV;
      v.z = accH[nf][2] + __low2float(l1)*LO_INV;
      v.w = accH[nf][3] + __high2float(l1)*LO_INV;
      *(float4*)(red + (((nf*4 + wks)*2 + wm)*32 + lane)*4) = v;
    }
    __syncthreads();

    float o00, o01, o10, o11;
    if (wks < 2){
      float4 p0 = *(const float4*)(red + (((nfw*4 + 0)*2 + wm)*32 + lane)*4);
      float4 p1 = *(const float4*)(red + (((nfw*4 + 1)*2 + wm)*32 + lane)*4);
      float4 p2 = *(const float4*)(red + (((nfw*4 + 2)*2 + wm)*32 + lane)*4);
      float4 p3 = *(const float4*)(red + (((nfw*4 + 3)*2 + wm)*32 + lane)*4);
      float s0 = (p0.x + p1.x) + (p2.x + p3.x);
      float s1 = (p0.y + p1.y) + (p2.y + p3.y);
      float s2 = (p0.z + p1.z) + (p2.z + p3.z);
      float s3 = (p0.w + p1.w) + (p2.w + p3.w);
      o00 = tanhf(s0 + pv0 + u_b0);
      o01 = tanhf(s1 + pv1 + u_b1);
      o10 = tanhf(s2 + pv2 + u_b0);
      o11 = tanhf(s3 + pv3 + u_b1);
    }

    if (t < SS-1){
      const int nb = (t & 1) ^ 1;
      if (wks < 2)
        *(uint2*)(&g_ha[nb][by][gA][wm][lslot]) = make_uint2(hpack(o00, o01), hpack(o10, o11));
      __syncthreads();   // A reads + red reads done; fragment STGs issued before release
      if (tid == 0)
        asm volatile("red.release.gpu.global.add.u32 [%0], %1;"
                     :: "l"(&g_wc[by][c_w][0]), "r"(1u) : "memory");
    } else if (wks < 2){
      g_h[(size_t)mr*HH + nc]       = o00;
      g_h[(size_t)mr*HH + nc + 1]   = o01;
      g_h[(size_t)(mr+8)*HH + nc]   = o10;
      g_h[(size_t)(mr+8)*HH + nc+1] = o11;
    }
  }
}

__global__ void k_final(const float* __restrict__ Vw, const float* __restrict__ Vb, float* __restrict__ out){
  int b = blockIdx.x;
  const float* h = g_h + (size_t)b*HH;
  float s = 0.f;
  for (int k = threadIdx.x; k < HH; k += 128) s += h[k]*Vw[k];
  #pragma unroll
  for (int o=16;o;o>>=1) s += __shfl_down_sync(0xffffffffu, s, o);
  __shared__ float red[4];
  if ((threadIdx.x & 31) == 0) red[threadIdx.x>>5] = s;
  __syncthreads();
  if (threadIdx.x == 0){
    float tot = red[0]+red[1]+red[2]+red[3] + Vb[0];
    out[b] = 1.f/(1.f + expf(-tot));
  }
}

extern "C" void kernel_launch(void* const* d_in, const int* in_sizes, int n_in,
                              void* d_out, int out_size){
  (void)in_sizes; (void)n_in; (void)out_size;
  const int*   x   = (const int*)d_in[0];
  const float* emb = (const float*)d_in[1];
  const float* Ww  = (const float*)d_in[2];
  const float* Wb  = (const float*)d_in[3];
  const float* Uw  = (const float*)d_in[4];
  const float* Ubv = (const float*)d_in[5];
  const float* Vw  = (const float*)d_in[6];
  const float* Vb  = (const float*)d_in[7];
  float* out = (float*)d_out;

  static bool attr_done = false;
  if (!attr_done){
    cudaFuncSetAttribute(k_scan, cudaFuncAttributeMaxDynamicSharedMemorySize, SMEM_BYTES);
    attr_done = true;
  }

  k_init<<<256, 256>>>();
  k_cvt<<<2048, 256>>>(emb, Ww);
  k_pre<<<dim3(HH/64, TOK/64), 256>>>(x, Wb);
  k_scan<<<dim3(64, 4), 256, SMEM_BYTES>>>(Uw, Ubv);
  k_final<<<BB, 128>>>(Vw, Vb, out);
}

// round 17
// speedup vs baseline: 4.5639x; 1.0255x over previous
#include <cuda_runtime.h>
#include <cuda_fp16.h>
#include <cstdint>

#define BB 128
#define SS 512
#define EE 512
#define HH 1024
#define VOCAB 32000
#define TOK (BB*SS)

// Scratch (allocation-free rule: __device__ globals)
__device__ float g_pre[(size_t)TOK * HH];        // [s*B + b][h], fp32
__device__ float g_h[BB * HH];                   // final hidden state
__device__ unsigned short g_emb16[(size_t)VOCAB * EE];  // fp16 embedding table
__device__ unsigned short g_w16[(size_t)HH * EE];       // fp16 W weights
// packed A fragments (fp16 h): [buf][mgroup][g(64 k16-groups)][wm][lane*4+word] fp16x2 words
__device__ __align__(16) unsigned g_ha[2][4][64][2][128];
// per-(mgroup, chunk) monotonic write counters, padded to 128B lines
__device__ unsigned g_wc[4][8][32];

__device__ __forceinline__ void mma16h(float c[4], uint4 a, unsigned b0, unsigned b1){
  asm volatile("mma.sync.aligned.m16n8k16.row.col.f32.f16.f16.f32 "
    "{%0,%1,%2,%3}, {%4,%5,%6,%7}, {%8,%9}, {%0,%1,%2,%3};"
    : "+f"(c[0]),"+f"(c[1]),"+f"(c[2]),"+f"(c[3])
    : "r"(a.x),"r"(a.y),"r"(a.z),"r"(a.w),"r"(b0),"r"(b1));
}
__device__ __forceinline__ void mma16hh(unsigned c[2], uint4 a, unsigned b0, unsigned b1){
  asm volatile("mma.sync.aligned.m16n8k16.row.col.f16.f16.f16.f16 "
    "{%0,%1}, {%2,%3,%4,%5}, {%6,%7}, {%0,%1};"
    : "+r"(c[0]),"+r"(c[1])
    : "r"(a.x),"r"(a.y),"r"(a.z),"r"(a.w),"r"(b0),"r"(b1));
}
__device__ __forceinline__ unsigned hpack(float x, float y){
  return (unsigned)__half_as_ushort(__float2half_rn(x))
       | ((unsigned)__half_as_ushort(__float2half_rn(y)) << 16);
}
__device__ __forceinline__ void waitflag(const unsigned* p, unsigned tgt){
  unsigned v;
  do { asm volatile("ld.global.acquire.gpu.u32 %0, [%1];" : "=r"(v) : "l"(p) : "memory"); } while (v < tgt);
}
__device__ __forceinline__ uint4 ldgcg4(const unsigned* p){
  uint4 v;
  asm volatile("ld.global.cg.v4.u32 {%0,%1,%2,%3}, [%4];"
    : "=r"(v.x),"=r"(v.y),"=r"(v.z),"=r"(v.w) : "l"(p));
  return v;
}

__global__ void k_init(){
  int i = blockIdx.x*blockDim.x + threadIdx.x;
  if (i < 16384) ((uint4*)g_ha)[i] = make_uint4(0,0,0,0);
  if (i < 4*8*32) ((unsigned*)g_wc)[i] = 0u;
}

// one-time fp32 -> fp16 conversion of emb and W (vectorized, grid-stride) -- R16-proven
__global__ void k_cvt(const float* __restrict__ emb, const float* __restrict__ Ww){
  const size_t NE = (size_t)VOCAB*EE/4, NW = (size_t)HH*EE/4;
  size_t stride = (size_t)gridDim.x*blockDim.x;
  for (size_t i = blockIdx.x*blockDim.x + threadIdx.x; i < NE; i += stride){
    float4 v = ((const float4*)emb)[i];
    ((uint2*)g_emb16)[i] = make_uint2(hpack(v.x, v.y), hpack(v.z, v.w));
  }
  for (size_t i = blockIdx.x*blockDim.x + threadIdx.x; i < NW; i += stride){
    float4 v = ((const float4*)Ww)[i];
    ((uint2*)g_w16)[i] = make_uint2(hpack(v.x, v.y), hpack(v.z, v.w));
  }
}

// pre[s*B+b][h] = dot(emb[x[b][s]], W[h]) + Wb[h]  (fp16 operands pre-converted) -- R16-proven
__global__ __launch_bounds__(256) void k_pre(const int* __restrict__ x, const float* __restrict__ Wb){
  __shared__ unsigned Ash[64][17];
  __shared__ unsigned Bsh[64][17];
  __shared__ const unsigned short* rowp[64];
  const int tid = threadIdx.x;
  const int m0 = blockIdx.y*64, n0 = blockIdx.x*64;
  if (tid < 64){
    int tok = m0 + tid;
    int b = tok & (BB-1), s = tok >> 7;
    rowp[tid] = g_emb16 + (size_t)x[b*SS + s]*EE;
  }
  __syncthreads();
  const int lane = tid & 31, wid = tid >> 5;
  const int wm = wid >> 1, wn = wid & 1;
  const int gr = lane >> 2, gq = lane & 3;
  const int lr = tid >> 2, lc = (tid & 3);
  float acc[4][4];
  #pragma unroll
  for (int i=0;i<4;i++){ acc[i][0]=0.f; acc[i][1]=0.f; acc[i][2]=0.f; acc[i][3]=0.f; }

  for (int kt = 0; kt < EE/32; ++kt){
    const int kh = kt*32 + lc*8;
    {
      uint4 av = *(const uint4*)(rowp[lr] + kh);
      Ash[lr][lc*4+0] = av.x; Ash[lr][lc*4+1] = av.y;
      Ash[lr][lc*4+2] = av.z; Ash[lr][lc*4+3] = av.w;
      uint4 bv = *(const uint4*)(g_w16 + (size_t)(n0+lr)*EE + kh);
      Bsh[lr][lc*4+0] = bv.x; Bsh[lr][lc*4+1] = bv.y;
      Bsh[lr][lc*4+2] = bv.z; Bsh[lr][lc*4+3] = bv.w;
    }
    __syncthreads();
    #pragma unroll
    for (int g = 0; g < 2; ++g){
      uint4 a;
      a.x = Ash[wm*16+gr  ][g*8+gq];
      a.y = Ash[wm*16+gr+8][g*8+gq];
      a.z = Ash[wm*16+gr  ][g*8+gq+4];
      a.w = Ash[wm*16+gr+8][g*8+gq+4];
      #pragma unroll
      for (int nf=0; nf<4; ++nf){
        int nr = wn*32 + nf*8 + gr;
        mma16h(acc[nf], a, Bsh[nr][g*8+gq], Bsh[nr][g*8+gq+4]);
      }
    }
    __syncthreads();
  }
  #pragma unroll
  for (int nf=0; nf<4; ++nf){
    int nc = n0 + wn*32 + nf*8 + 2*gq;
    int mr = m0 + wm*16 + gr;
    float wb0 = Wb[nc], wb1 = Wb[nc+1];
    g_pre[(size_t)mr*HH + nc]        = acc[nf][0] + wb0;
    g_pre[(size_t)mr*HH + nc + 1]    = acc[nf][1] + wb1;
    g_pre[(size_t)(mr+8)*HH + nc]    = acc[nf][2] + wb0;
    g_pre[(size_t)(mr+8)*HH + nc+1]  = acc[nf][3] + wb1;
  }
}

// ---------------- persistent recurrence: R15-proven m x k warp tiling ----------------
// 128 CTAs = 4 mgroups (by) x 32 n-slices (bx). 256 threads, 8 warps.
// Warps: wm = wid&1 (m-half), wks = wid>>1 (k-quarter). Warp tile m16 x n32 x k256:
// each A fragment LDG'd from L2 exactly ONCE per CTA (8MB/step chip-wide).
// D_H(f32) += a*bh ; D_L(f16 acc) += a*(4096*bl) ; s = D_H + D_L/4096.
#define SM_B   0
#define SM_UB  131072
#define SM_RED 131200
#define SMEM_BYTES 147584
#define LO_SCALE 4096.0f
#define LO_INV   (1.0f/4096.0f)

__global__ __launch_bounds__(256, 1) void k_scan(const float* __restrict__ U, const float* __restrict__ Ub){
  extern __shared__ unsigned smw[];   // word-addressed
  const int tid = threadIdx.x, lane = tid & 31, wid = tid >> 5;
  const int gr = lane >> 2, gq = lane & 3;
  const int wm = wid & 1, wks = wid >> 1;       // 2 m-halves x 4 k-quarters
  const int bx = blockIdx.x, by = blockIdx.y;
  const int n0 = bx*32, m0 = by*32;

  // ---- pack U slice (rows n0..n0+31, full K) into fp16 hi + scaled-lo B-fragments ----
  for (int e = tid; e < 64*4*32; e += 256){
    int ln = e & 31, nf = (e >> 5) & 3, g = e >> 7;
    int rr = ln >> 2, qq = ln & 3;
    const float* ur = U + (size_t)(n0 + nf*8 + rr)*HH + g*16 + 2*qq;
    float v0 = ur[0], v1 = ur[1], v2 = ur[8], v3 = ur[9];
    float h0 = __half2float(__float2half_rn(v0));
    float h1 = __half2float(__float2half_rn(v1));
    float h2 = __half2float(__float2half_rn(v2));
    float h3 = __half2float(__float2half_rn(v3));
    unsigned bh0 = hpack(v0, v1), bh1 = hpack(v2, v3);
    unsigned bl0 = hpack((v0-h0)*LO_SCALE, (v1-h1)*LO_SCALE);
    unsigned bl1 = hpack((v2-h2)*LO_SCALE, (v3-h3)*LO_SCALE);
    unsigned off = (unsigned)(((g*4 + nf)*32 + ln)*4);
    *(uint4*)(smw + SM_B/4 + off) = make_uint4(bh0, bh1, bl0, bl1);
  }
  if (tid < 32) ((float*)(smw + SM_UB/4))[tid] = Ub[n0 + tid];

  // epilogue / producer constants (R15-proven)
  const int nc = n0 + wks*8 + 2*gq;             // output columns nc, nc+1
  const int mr = m0 + wm*16 + gr;               // output rows mr, mr+8
  const float u_b0 = Ub[nc], u_b1 = Ub[nc+1];
  const int gA = bx*2 + (wks >> 1);             // destination k16-group of columns nc
  const int wbase = (wks & 1)*2;
  const int lslot = (gr*4 + gq)*4 + wbase;
  const int c_w = bx >> 2;                      // this CTA's write chunk
  float* red = (float*)(smw + SM_RED/4);        // [nf][q][wm][lane][4]
  __syncthreads();

  for (int t = 0; t < SS; ++t){
    const unsigned* ga = &g_ha[t & 1][by][0][0][0];   // 16384 words, fragment-packed
    const float* __restrict__ pre = g_pre + (size_t)t*BB*HH;
    const unsigned tgt = 4u*(unsigned)t;

    const float pv0 = pre[(size_t)mr*HH + nc];
    const float pv1 = pre[(size_t)mr*HH + nc + 1];
    const float pv2 = pre[(size_t)(mr+8)*HH + nc];
    const float pv3 = pre[(size_t)(mr+8)*HH + nc + 1];

    // gate: this warp only needs chunks wks*2, wks*2+1 (its 16 k-groups)
    if (lane < 2) waitflag(&g_wc[by][wks*2 + lane][0], tgt);
    __syncwarp();

    float accH[4][4];
    unsigned accL[4][2];
    #pragma unroll
    for (int i=0;i<4;++i){
      accH[i][0]=0.f;accH[i][1]=0.f;accH[i][2]=0.f;accH[i][3]=0.f;
      accL[i][0]=0u; accL[i][1]=0u;
    }

    // 16 k16 groups x 4 n-fragments; A read once per CTA
    const unsigned* bp = smw + SM_B/4;
    #pragma unroll
    for (int gl = 0; gl < 16; ++gl){
      const int g = wks*16 + gl;
      uint4 a = ldgcg4(ga + ((g*2 + wm)*32 + lane)*4);
      #pragma unroll
      for (int nf = 0; nf < 4; ++nf){
        uint4 b = *(const uint4*)(bp + ((g*4 + nf)*32 + lane)*4);
        mma16h(accH[nf], a, b.x, b.y);
        mma16hh(accL[nf], a, b.z, b.w);
      }
    }

    // ---- k-quarter reduction via SMEM ----
    #pragma unroll
    for (int nf = 0; nf < 4; ++nf){
      __half2 l0 = *(__half2*)&accL[nf][0];
      __half2 l1 = *(__half2*)&accL[nf][1];
      float4 v;
      v.x = accH[nf][0] + __low2float(l0)*LO_INV;
      v.y = accH[nf][1] + __high2float(l0)*LO_INV;
      v.z = accH[nf][2] + __low2float(l1)*LO_INV;
      v.w = accH[nf][3] + __high2float(l1)*LO_INV;
      *(float4*)(red + (((nf*4 + wks)*2 + wm)*32 + lane)*4) = v;
    }
    __syncthreads();
    float4 p0 = *(const float4*)(red + (((wks*4 + 0)*2 + wm)*32 + lane)*4);
    float4 p1 = *(const float4*)(red + (((wks*4 + 1)*2 + wm)*32 + lane)*4);
    float4 p2 = *(const float4*)(red + (((wks*4 + 2)*2 + wm)*32 + lane)*4);
    float4 p3 = *(const float4*)(red + (((wks*4 + 3)*2 + wm)*32 + lane)*4);
    float s0 = (p0.x + p1.x) + (p2.x + p3.x);
    float s1 = (p0.y + p1.y) + (p2.y + p3.y);
    float s2 = (p0.z + p1.z) + (p2.z + p3.z);
    float s3 = (p0.w + p1.w) + (p2.w + p3.w);

    float o00 = tanhf(s0 + pv0 + u_b0);
    float o01 = tanhf(s1 + pv1 + u_b1);
    float o10 = tanhf(s2 + pv2 + u_b0);
    float o11 = tanhf(s3 + pv3 + u_b1);

    if (t < SS-1){
      const int nb = (t & 1) ^ 1;
      *(uint2*)(&g_ha[nb][by][gA][wm][lslot]) = make_uint2(hpack(o00, o01), hpack(o10, o11));
      __syncthreads();   // A reads + red reads done; fragment STGs issued before release
      if (tid == 0)
        asm volatile("red.release.gpu.global.add.u32 [%0], %1;"
                     :: "l"(&g_wc[by][c_w][0]), "r"(1u) : "memory");
    } else {
      g_h[(size_t)mr*HH + nc]       = o00;
      g_h[(size_t)mr*HH + nc + 1]   = o01;
      g_h[(size_t)(mr+8)*HH + nc]   = o10;
      g_h[(size_t)(mr+8)*HH + nc+1] = o11;
    }
  }
}

__global__ void k_final(const float* __restrict__ Vw, const float* __restrict__ Vb, float* __restrict__ out){
  int b = blockIdx.x;
  const float* h = g_h + (size_t)b*HH;
  float s = 0.f;
  for (int k = threadIdx.x; k < HH; k += 128) s += h[k]*Vw[k];
  #pragma unroll
  for (int o=16;o;o>>=1) s += __shfl_down_sync(0xffffffffu, s, o);
  __shared__ float red[4];
  if ((threadIdx.x & 31) == 0) red[threadIdx.x>>5] = s;
  __syncthreads();
  if (threadIdx.x == 0){
    float tot = red[0]+red[1]+red[2]+red[3] + Vb[0];
    out[b] = 1.f/(1.f + expf(-tot));
  }
}

extern "C" void kernel_launch(void* const* d_in, const int* in_sizes, int n_in,
                              void* d_out, int out_size){
  (void)in_sizes; (void)n_in; (void)out_size;
  const int*   x   = (const int*)d_in[0];
  const float* emb = (const float*)d_in[1];
  const float* Ww  = (const float*)d_in[2];
  const float* Wb  = (const float*)d_in[3];
  const float* Uw  = (const float*)d_in[4];
  const float* Ubv = (const float*)d_in[5];
  const float* Vw  = (const float*)d_in[6];
  const float* Vb  = (const float*)d_in[7];
  float* out = (float*)d_out;

  static bool attr_done = false;
  if (!attr_done){
    cudaFuncSetAttribute(k_scan, cudaFuncAttributeMaxDynamicSharedMemorySize, SMEM_BYTES);
    attr_done = true;
  }

  k_init<<<256, 256>>>();
  k_cvt<<<2048, 256>>>(emb, Ww);
  k_pre<<<dim3(HH/64, TOK/64), 256>>>(x, Wb);
  k_scan<<<dim3(32, 4), 256, SMEM_BYTES>>>(Uw, Ubv);
  k_final<<<BB, 128>>>(Vw, Vb, out);
}